// round 1
// baseline (speedup 1.0000x reference)
#include <cuda_runtime.h>
#include <math.h>

#define Bn   32
#define Sn   512
#define Dn   1024
#define Hn   16
#define DKn  64
#define BH   (Bn*Hn)                 // 512
#define CTX_ELEMS (Bn*Sn*Dn)         // 16,777,216
#define ATT_ELEMS ((size_t)Bn*Hn*Sn*Sn) // 134,217,728

// Scratch (allocation-free per harness rules)
__device__ float g_q[CTX_ELEMS];
__device__ float g_k[CTX_ELEMS];
__device__ float g_v[CTX_ELEMS];
__device__ float g_rowsum[BH*Sn];            // 262,144
__device__ float g_attn_fallback[ATT_ELEMS]; // used only if attn not in d_out

// ---------------------------------------------------------------------------
// Kernel 1: QKV projection. C[n,i] = sum_k X[n,k]*W[i,k] + bias[i]
// 128x128 tile, K-tile 8, 256 threads, 8x8 per thread.
// Output written in [B,H,S,DK] layout. blockIdx.z selects q/k/v.
// ---------------------------------------------------------------------------
__global__ __launch_bounds__(256) void qkv_kernel(
    const float* __restrict__ X,
    const float* __restrict__ Wq, const float* __restrict__ bq,
    const float* __restrict__ Wk, const float* __restrict__ bk,
    const float* __restrict__ Wv, const float* __restrict__ bv)
{
    const float* W; const float* bias; float* out;
    if      (blockIdx.z == 0) { W = Wq; bias = bq; out = g_q; }
    else if (blockIdx.z == 1) { W = Wk; bias = bk; out = g_k; }
    else                      { W = Wv; bias = bv; out = g_v; }

    __shared__ __align__(16) float As[8][132];
    __shared__ __align__(16) float Bs[8][132];

    const int bm = blockIdx.y * 128;
    const int bn = blockIdx.x * 128;
    const int tid = threadIdx.x;
    const int tx = tid & 15;
    const int ty = tid >> 4;
    const int lr = tid >> 1;          // 0..127
    const int lc = (tid & 1) * 4;     // 0 or 4

    const float* aptr = X + (size_t)(bm + lr) * Dn + lc;
    const float* bptr = W + (size_t)(bn + lr) * Dn + lc;

    float acc[8][8];
#pragma unroll
    for (int i = 0; i < 8; i++)
#pragma unroll
        for (int j = 0; j < 8; j++) acc[i][j] = 0.0f;

    for (int k0 = 0; k0 < Dn; k0 += 8) {
        float4 av = *(const float4*)(aptr + k0);
        float4 bv4 = *(const float4*)(bptr + k0);
        __syncthreads();
        As[lc+0][lr] = av.x;  As[lc+1][lr] = av.y;
        As[lc+2][lr] = av.z;  As[lc+3][lr] = av.w;
        Bs[lc+0][lr] = bv4.x; Bs[lc+1][lr] = bv4.y;
        Bs[lc+2][lr] = bv4.z; Bs[lc+3][lr] = bv4.w;
        __syncthreads();
#pragma unroll
        for (int kk = 0; kk < 8; kk++) {
            float4 a0 = *(const float4*)&As[kk][ty*8];
            float4 a1 = *(const float4*)&As[kk][ty*8+4];
            float4 b0 = *(const float4*)&Bs[kk][tx*8];
            float4 b1 = *(const float4*)&Bs[kk][tx*8+4];
            float a[8] = {a0.x,a0.y,a0.z,a0.w,a1.x,a1.y,a1.z,a1.w};
            float b[8] = {b0.x,b0.y,b0.z,b0.w,b1.x,b1.y,b1.z,b1.w};
#pragma unroll
            for (int i = 0; i < 8; i++)
#pragma unroll
                for (int j = 0; j < 8; j++)
                    acc[i][j] = fmaf(a[i], b[j], acc[i][j]);
        }
    }

#pragma unroll
    for (int i = 0; i < 8; i++) {
        int n = bm + ty*8 + i;
        int b = n >> 9;          // /512
        int s = n & 511;
#pragma unroll
        for (int j = 0; j < 8; j += 4) {
            int ifeat = bn + tx*8 + j;
            int h  = ifeat >> 6;
            int dk = ifeat & 63;
            float4 v;
            v.x = acc[i][j]   + bias[ifeat];
            v.y = acc[i][j+1] + bias[ifeat+1];
            v.z = acc[i][j+2] + bias[ifeat+2];
            v.w = acc[i][j+3] + bias[ifeat+3];
            *(float4*)&out[((size_t)((b*Hn + h)*Sn + s)) * DKn + dk] = v;
        }
    }
}

// ---------------------------------------------------------------------------
// Kernel 2: E[bh,q,k] = exp(q·k / 8) * (k < length[b]); 64x64 tiles, DK=64.
// ---------------------------------------------------------------------------
__global__ __launch_bounds__(256) void scores_kernel(
    const int* __restrict__ length, float* __restrict__ attn)
{
    const int bh = blockIdx.z;
    const int b  = bh >> 4;
    const int q0 = blockIdx.y * 64;
    const int k0 = blockIdx.x * 64;
    const float* Qh = g_q + (size_t)bh * Sn * DKn;
    const float* Kh = g_k + (size_t)bh * Sn * DKn;

    __shared__ __align__(16) float Qs[64][68];
    __shared__ __align__(16) float Ks[64][68];

    const int tid = threadIdx.x;
#pragma unroll
    for (int r = 0; r < 4; r++) {
        int f   = tid + r*256;   // 0..1023 float4 index
        int row = f >> 4;
        int seg = (f & 15) * 4;
        float4 qv = *(const float4*)(Qh + (size_t)(q0+row)*DKn + seg);
        float4 kv = *(const float4*)(Kh + (size_t)(k0+row)*DKn + seg);
        Qs[seg+0][row]=qv.x; Qs[seg+1][row]=qv.y; Qs[seg+2][row]=qv.z; Qs[seg+3][row]=qv.w;
        Ks[seg+0][row]=kv.x; Ks[seg+1][row]=kv.y; Ks[seg+2][row]=kv.z; Ks[seg+3][row]=kv.w;
    }
    __syncthreads();

    const int tx = tid & 15;
    const int ty = tid >> 4;
    float acc[4][4];
#pragma unroll
    for (int i = 0; i < 4; i++)
#pragma unroll
        for (int j = 0; j < 4; j++) acc[i][j] = 0.0f;

#pragma unroll 16
    for (int kk = 0; kk < 64; kk++) {
        float4 a = *(const float4*)&Qs[kk][ty*4];
        float4 c = *(const float4*)&Ks[kk][tx*4];
        float av[4] = {a.x,a.y,a.z,a.w};
        float cv[4] = {c.x,c.y,c.z,c.w};
#pragma unroll
        for (int i = 0; i < 4; i++)
#pragma unroll
            for (int j = 0; j < 4; j++)
                acc[i][j] = fmaf(av[i], cv[j], acc[i][j]);
    }

    const int len = length[b];
#pragma unroll
    for (int i = 0; i < 4; i++) {
        int q = q0 + ty*4 + i;
        float4 v;
        float* vv = (float*)&v;
#pragma unroll
        for (int j = 0; j < 4; j++) {
            int kcol = k0 + tx*4 + j;
            vv[j] = (kcol < len) ? expf(acc[i][j] * 0.125f) : 0.0f;
        }
        *(float4*)&attn[((size_t)bh*Sn + q)*Sn + k0 + tx*4] = v;
    }
}

// ---------------------------------------------------------------------------
// Kernel 3: deterministic row sums (one warp per row of 512)
// ---------------------------------------------------------------------------
__global__ __launch_bounds__(256) void rowsum_kernel(const float* __restrict__ attn)
{
    int warp = (int)((blockIdx.x * 256 + threadIdx.x) >> 5);
    int lane = threadIdx.x & 31;
    if (warp >= BH*Sn) return;
    const float* row = attn + (size_t)warp * Sn;
    float p = 0.0f;
#pragma unroll
    for (int r = 0; r < 4; r++) {
        float4 t = *(const float4*)(row + lane*4 + r*128);
        p += t.x + t.y + t.z + t.w;
    }
    p += __shfl_xor_sync(0xffffffffu, p, 16);
    p += __shfl_xor_sync(0xffffffffu, p, 8);
    p += __shfl_xor_sync(0xffffffffu, p, 4);
    p += __shfl_xor_sync(0xffffffffu, p, 2);
    p += __shfl_xor_sync(0xffffffffu, p, 1);
    if (lane == 0) g_rowsum[warp] = p;
}

// ---------------------------------------------------------------------------
// Kernel 4: in-place normalize: attn /= (rowsum + 1e-8)
// ---------------------------------------------------------------------------
__global__ __launch_bounds__(256) void normalize_kernel(float* __restrict__ attn)
{
    size_t i4 = (size_t)blockIdx.x * 256 + threadIdx.x;   // float4 index
    int row = (int)(i4 >> 7);                             // 128 float4 per row
    float inv = 1.0f / (g_rowsum[row] + 1e-8f);
    float4* p = (float4*)attn;
    float4 v = p[i4];
    v.x *= inv; v.y *= inv; v.z *= inv; v.w *= inv;
    p[i4] = v;
}

// ---------------------------------------------------------------------------
// Kernel 5: context = attn @ V, per (b,h): [512,512]@[512,64]
// 64 q-rows per block, full DK=64, K-loop over 512 keys.
// Writes context in [B,S,D] layout.
// ---------------------------------------------------------------------------
__global__ __launch_bounds__(256) void av_kernel(
    const float* __restrict__ attn, float* __restrict__ ctx)
{
    const int bh = blockIdx.y;
    const int b  = bh >> 4;
    const int h  = bh & 15;
    const int q0 = blockIdx.x * 64;
    const float* Ah = attn + (size_t)bh * Sn * Sn;
    const float* Vh = g_v  + (size_t)bh * Sn * DKn;

    __shared__ __align__(16) float As[64][68];   // As[k][q]  (transposed)
    __shared__ __align__(16) float Vs[64][68];   // Vs[k][dk] (natural)

    const int tid = threadIdx.x;
    const int tx = tid & 15;
    const int ty = tid >> 4;
    float acc[4][4];
#pragma unroll
    for (int i = 0; i < 4; i++)
#pragma unroll
        for (int j = 0; j < 4; j++) acc[i][j] = 0.0f;

    for (int k0 = 0; k0 < Sn; k0 += 64) {
        float4 avv[4], vvv[4];
#pragma unroll
        for (int r = 0; r < 4; r++) {
            int f = tid + r*256;
            int row = f >> 4;
            int seg = (f & 15) * 4;
            avv[r] = *(const float4*)(Ah + (size_t)(q0+row)*Sn + k0 + seg);
            vvv[r] = *(const float4*)(Vh + (size_t)(k0+row)*DKn + seg);
        }
        __syncthreads();
#pragma unroll
        for (int r = 0; r < 4; r++) {
            int f = tid + r*256;
            int row = f >> 4;
            int seg = (f & 15) * 4;
            As[seg+0][row] = avv[r].x; As[seg+1][row] = avv[r].y;
            As[seg+2][row] = avv[r].z; As[seg+3][row] = avv[r].w;
            *(float4*)&Vs[row][seg] = vvv[r];
        }
        __syncthreads();
#pragma unroll 16
        for (int kk = 0; kk < 64; kk++) {
            float4 a = *(const float4*)&As[kk][ty*4];
            float4 c = *(const float4*)&Vs[kk][tx*4];
            float av[4] = {a.x,a.y,a.z,a.w};
            float cv[4] = {c.x,c.y,c.z,c.w};
#pragma unroll
            for (int i = 0; i < 4; i++)
#pragma unroll
                for (int j = 0; j < 4; j++)
                    acc[i][j] = fmaf(av[i], cv[j], acc[i][j]);
        }
        __syncthreads();
    }

#pragma unroll
    for (int i = 0; i < 4; i++) {
        int s = q0 + ty*4 + i;
        float4 v;
        v.x = acc[i][0]; v.y = acc[i][1]; v.z = acc[i][2]; v.w = acc[i][3];
        *(float4*)&ctx[((size_t)(b*Sn + s))*Dn + h*DKn + tx*4] = v;
    }
}

// ---------------------------------------------------------------------------
extern "C" void kernel_launch(void* const* d_in, const int* in_sizes, int n_in,
                              void* d_out, int out_size)
{
    const float* Q   = (const float*)d_in[0];
    const float* Wq  = (const float*)d_in[1];
    const float* bq  = (const float*)d_in[2];
    const float* Wk  = (const float*)d_in[3];
    const float* bk  = (const float*)d_in[4];
    const float* Wv  = (const float*)d_in[5];
    const float* bv  = (const float*)d_in[6];
    const int*   len = (const int*)d_in[7];

    float* ctx = (float*)d_out;
    float* attn;
    if ((size_t)out_size >= (size_t)CTX_ELEMS + ATT_ELEMS) {
        attn = ctx + CTX_ELEMS;   // tuple output: [context | attn]
    } else {
        // attn not part of output: use device scratch
        void* p = nullptr;
        cudaGetSymbolAddress(&p, g_attn_fallback);
        attn = (float*)p;
    }

    // 1) QKV projections (z = 0:q, 1:k, 2:v)
    qkv_kernel<<<dim3(Dn/128, (Bn*Sn)/128, 3), 256>>>(Q, Wq, bq, Wk, bk, Wv, bv);
    // 2) exp(scores)*mask
    scores_kernel<<<dim3(Sn/64, Sn/64, BH), 256>>>(len, attn);
    // 3) deterministic row sums
    rowsum_kernel<<<dim3((BH*Sn)/8), 256>>>(attn);
    // 4) normalize in place
    normalize_kernel<<<dim3((unsigned)(ATT_ELEMS/4/256)), 256>>>(attn);
    // 5) context = attn @ V
    av_kernel<<<dim3(Sn/64, BH), 256>>>(attn, ctx);
}

// round 2
// speedup vs baseline: 1.1029x; 1.1029x over previous
#include <cuda_runtime.h>
#include <math.h>

#define Bn   32
#define Sn   512
#define Dn   1024
#define Hn   16
#define DKn  64
#define BH   (Bn*Hn)                 // 512
#define CTX_ELEMS (Bn*Sn*Dn)         // 16,777,216
#define ATT_ELEMS ((size_t)Bn*Hn*Sn*Sn) // 134,217,728

// Scratch (allocation-free per harness rules)
__device__ float g_q[CTX_ELEMS];
__device__ float g_k[CTX_ELEMS];
__device__ float g_v[CTX_ELEMS];
__device__ float g_rowsum[BH*Sn];            // 262,144
__device__ float g_part[(size_t)BH*Sn*4];    // per-ktile row partials (4MB)
__device__ float g_attn_fallback[ATT_ELEMS]; // used only if attn not in d_out

// ---------------------------------------------------------------------------
// packed fp32x2 helpers (Blackwell: doubles fp32 FMA throughput; ptxas never
// auto-emits FFMA2, must come from PTX fma.rn.f32x2)
// ---------------------------------------------------------------------------
typedef unsigned long long u64;

__device__ __forceinline__ u64 pack2(float x, float y) {
    u64 r; asm("mov.b64 %0,{%1,%2};" : "=l"(r) : "f"(x), "f"(y)); return r;
}
__device__ __forceinline__ void unpack2(u64 v, float& x, float& y) {
    asm("mov.b64 {%0,%1},%2;" : "=f"(x), "=f"(y) : "l"(v));
}
__device__ __forceinline__ u64 ffma2(u64 a, u64 b, u64 c) {
    u64 d; asm("fma.rn.f32x2 %0,%1,%2,%3;" : "=l"(d) : "l"(a), "l"(b), "l"(c)); return d;
}

// ---------------------------------------------------------------------------
// Kernel 1: QKV projection. C[n,i] = sum_k X[n,k]*W[i,k] + bias[i]
// 128x128 tile, K-tile 8, 256 threads, 8x8 per thread, f32x2 inner loop.
// Output written in [B,H,S,DK] layout. blockIdx.z selects q/k/v.
// ---------------------------------------------------------------------------
__global__ __launch_bounds__(256, 2) void qkv_kernel(
    const float* __restrict__ X,
    const float* __restrict__ Wq, const float* __restrict__ bq,
    const float* __restrict__ Wk, const float* __restrict__ bk,
    const float* __restrict__ Wv, const float* __restrict__ bv)
{
    const float* W; const float* bias; float* out;
    if      (blockIdx.z == 0) { W = Wq; bias = bq; out = g_q; }
    else if (blockIdx.z == 1) { W = Wk; bias = bk; out = g_k; }
    else                      { W = Wv; bias = bv; out = g_v; }

    __shared__ __align__(16) float As[8][132];
    __shared__ __align__(16) float Bs[8][132];

    const int bm = blockIdx.y * 128;
    const int bn = blockIdx.x * 128;
    const int tid = threadIdx.x;
    const int tx = tid & 15;
    const int ty = tid >> 4;
    const int lr = tid >> 1;          // 0..127
    const int lc = (tid & 1) * 4;     // 0 or 4

    const float* aptr = X + (size_t)(bm + lr) * Dn + lc;
    const float* bptr = W + (size_t)(bn + lr) * Dn + lc;

    u64 acc2[4][8];
#pragma unroll
    for (int i = 0; i < 4; i++)
#pragma unroll
        for (int j = 0; j < 8; j++) acc2[i][j] = 0ull;

    for (int k0 = 0; k0 < Dn; k0 += 8) {
        float4 av  = *(const float4*)(aptr + k0);
        float4 bv4 = *(const float4*)(bptr + k0);
        __syncthreads();
        As[lc+0][lr] = av.x;  As[lc+1][lr] = av.y;
        As[lc+2][lr] = av.z;  As[lc+3][lr] = av.w;
        Bs[lc+0][lr] = bv4.x; Bs[lc+1][lr] = bv4.y;
        Bs[lc+2][lr] = bv4.z; Bs[lc+3][lr] = bv4.w;
        __syncthreads();
#pragma unroll
        for (int kk = 0; kk < 8; kk++) {
            ulonglong2 a01 = *(const ulonglong2*)&As[kk][ty*8];
            ulonglong2 a23 = *(const ulonglong2*)&As[kk][ty*8+4];
            u64 a2r[4] = {a01.x, a01.y, a23.x, a23.y};
            float4 b0 = *(const float4*)&Bs[kk][tx*8];
            float4 b1 = *(const float4*)&Bs[kk][tx*8+4];
            u64 bb[8] = {pack2(b0.x,b0.x), pack2(b0.y,b0.y), pack2(b0.z,b0.z), pack2(b0.w,b0.w),
                         pack2(b1.x,b1.x), pack2(b1.y,b1.y), pack2(b1.z,b1.z), pack2(b1.w,b1.w)};
#pragma unroll
            for (int i = 0; i < 4; i++)
#pragma unroll
                for (int j = 0; j < 8; j++)
                    acc2[i][j] = ffma2(a2r[i], bb[j], acc2[i][j]);
        }
    }

    float acc[8][8];
#pragma unroll
    for (int i2 = 0; i2 < 4; i2++)
#pragma unroll
        for (int j = 0; j < 8; j++)
            unpack2(acc2[i2][j], acc[2*i2][j], acc[2*i2+1][j]);

#pragma unroll
    for (int i = 0; i < 8; i++) {
        int n = bm + ty*8 + i;
        int b = n >> 9;          // /512
        int s = n & 511;
#pragma unroll
        for (int j = 0; j < 8; j += 4) {
            int ifeat = bn + tx*8 + j;
            int h  = ifeat >> 6;
            int dk = ifeat & 63;
            float4 v;
            v.x = acc[i][j]   + bias[ifeat];
            v.y = acc[i][j+1] + bias[ifeat+1];
            v.z = acc[i][j+2] + bias[ifeat+2];
            v.w = acc[i][j+3] + bias[ifeat+3];
            *(float4*)&out[((size_t)((b*Hn + h)*Sn + s)) * DKn + dk] = v;
        }
    }
}

// ---------------------------------------------------------------------------
// Kernel 2: E[bh,q,k] = exp(q·k / 8) * (k < length[b])
// 128x128 tiles, contraction over DK=64 in chunks of 8. f32x2 inner loop.
// Also emits per-(row, k-tile) partial sums to g_part (fused rowsum).
// ---------------------------------------------------------------------------
__global__ __launch_bounds__(256, 2) void scores_kernel(
    const int* __restrict__ length, float* __restrict__ attn)
{
    const int bh = blockIdx.z;
    const int b  = bh >> 4;
    const int q0 = blockIdx.y * 128;
    const int k0 = blockIdx.x * 128;
    const float* Qh = g_q + (size_t)bh * Sn * DKn;
    const float* Kh = g_k + (size_t)bh * Sn * DKn;

    __shared__ __align__(16) float As[8][132];  // As[dk][q]
    __shared__ __align__(16) float Bs[8][132];  // Bs[dk][kcol]

    const int tid = threadIdx.x;
    const int tx = tid & 15;
    const int ty = tid >> 4;
    const int lr = tid >> 1;
    const int lc = (tid & 1) * 4;

    const float* aptr = Qh + (size_t)(q0 + lr) * DKn + lc;
    const float* bptr = Kh + (size_t)(k0 + lr) * DKn + lc;

    u64 acc2[4][8];
#pragma unroll
    for (int i = 0; i < 4; i++)
#pragma unroll
        for (int j = 0; j < 8; j++) acc2[i][j] = 0ull;

#pragma unroll
    for (int d0 = 0; d0 < DKn; d0 += 8) {
        float4 av  = *(const float4*)(aptr + d0);
        float4 bv4 = *(const float4*)(bptr + d0);
        __syncthreads();
        As[lc+0][lr] = av.x;  As[lc+1][lr] = av.y;
        As[lc+2][lr] = av.z;  As[lc+3][lr] = av.w;
        Bs[lc+0][lr] = bv4.x; Bs[lc+1][lr] = bv4.y;
        Bs[lc+2][lr] = bv4.z; Bs[lc+3][lr] = bv4.w;
        __syncthreads();
#pragma unroll
        for (int kk = 0; kk < 8; kk++) {
            ulonglong2 a01 = *(const ulonglong2*)&As[kk][ty*8];
            ulonglong2 a23 = *(const ulonglong2*)&As[kk][ty*8+4];
            u64 a2r[4] = {a01.x, a01.y, a23.x, a23.y};
            float4 b0 = *(const float4*)&Bs[kk][tx*8];
            float4 b1 = *(const float4*)&Bs[kk][tx*8+4];
            u64 bb[8] = {pack2(b0.x,b0.x), pack2(b0.y,b0.y), pack2(b0.z,b0.z), pack2(b0.w,b0.w),
                         pack2(b1.x,b1.x), pack2(b1.y,b1.y), pack2(b1.z,b1.z), pack2(b1.w,b1.w)};
#pragma unroll
            for (int i = 0; i < 4; i++)
#pragma unroll
                for (int j = 0; j < 8; j++)
                    acc2[i][j] = ffma2(a2r[i], bb[j], acc2[i][j]);
        }
    }

    float acc[8][8];
#pragma unroll
    for (int i2 = 0; i2 < 4; i2++)
#pragma unroll
        for (int j = 0; j < 8; j++)
            unpack2(acc2[i2][j], acc[2*i2][j], acc[2*i2+1][j]);

    const int len = length[b];
#pragma unroll
    for (int i = 0; i < 8; i++) {
        int q = q0 + ty*8 + i;
        float e[8];
        float rp = 0.0f;
#pragma unroll
        for (int j = 0; j < 8; j++) {
            int kcol = k0 + tx*8 + j;
            e[j] = (kcol < len) ? expf(acc[i][j] * 0.125f) : 0.0f;
            rp += e[j];
        }
        float4 v0 = make_float4(e[0], e[1], e[2], e[3]);
        float4 v1 = make_float4(e[4], e[5], e[6], e[7]);
        float* dst = &attn[((size_t)bh*Sn + q)*Sn + k0 + tx*8];
        *(float4*)dst       = v0;
        *(float4*)(dst + 4) = v1;
        // reduce row partial across the 16 tx threads (half-warp)
        rp += __shfl_xor_sync(0xffffffffu, rp, 8);
        rp += __shfl_xor_sync(0xffffffffu, rp, 4);
        rp += __shfl_xor_sync(0xffffffffu, rp, 2);
        rp += __shfl_xor_sync(0xffffffffu, rp, 1);
        if (tx == 0)
            g_part[((size_t)bh*Sn + q)*4 + blockIdx.x] = rp;
    }
}

// ---------------------------------------------------------------------------
// Kernel 3: finish rowsums (4 partials per row)
// ---------------------------------------------------------------------------
__global__ __launch_bounds__(256) void rowsum_reduce_kernel()
{
    int r = blockIdx.x * 256 + threadIdx.x;
    if (r < BH*Sn) {
        float4 p = *(const float4*)&g_part[(size_t)r*4];
        g_rowsum[r] = p.x + p.y + p.z + p.w;
    }
}

// ---------------------------------------------------------------------------
// Kernel 4: context = (E * inv) @ V, fused normalize (writes normalized attn
// back in place). Per (bh, 256-q tile): [256,512]@[512,64]. f32x2 inner loop.
// ---------------------------------------------------------------------------
__global__ __launch_bounds__(256, 2) void av_kernel(
    float* __restrict__ attn, float* __restrict__ ctx)
{
    const int bh = blockIdx.y;
    const int b  = bh >> 4;
    const int h  = bh & 15;
    const int q0 = blockIdx.x * 256;
    float* Ah = attn + ((size_t)bh*Sn + q0) * Sn;
    const float* Vh = g_v + (size_t)bh * Sn * DKn;

    __shared__ __align__(16) float As[8][264];  // As[kk][q]  (keys x 256 q-rows)
    __shared__ __align__(16) float Bs[8][68];   // Bs[kk][dk]
    __shared__ float invS[256];

    const int tid = threadIdx.x;
    const int tx = tid & 7;          // 8 dk groups of 8
    const int ty = tid >> 3;         // 32 q groups of 8
    const int lr = tid >> 1;         // 0..127
    const int lc = (tid & 1) * 4;    // 0 or 4

    invS[tid] = 1.0f / (g_rowsum[(size_t)bh*Sn + q0 + tid] + 1e-8f);
    __syncthreads();
    const float inv0 = invS[lr];
    const float inv1 = invS[lr + 128];

    u64 acc2[4][8];
#pragma unroll
    for (int i = 0; i < 4; i++)
#pragma unroll
        for (int j = 0; j < 8; j++) acc2[i][j] = 0ull;

    for (int k0 = 0; k0 < Sn; k0 += 8) {
        // load + scale + write-back normalized attn (each elem touched once)
        float4 a0 = *(const float4*)(Ah + (size_t)lr       *Sn + k0 + lc);
        float4 a1 = *(const float4*)(Ah + (size_t)(lr+128) *Sn + k0 + lc);
        a0.x *= inv0; a0.y *= inv0; a0.z *= inv0; a0.w *= inv0;
        a1.x *= inv1; a1.y *= inv1; a1.z *= inv1; a1.w *= inv1;
        *(float4*)(Ah + (size_t)lr      *Sn + k0 + lc) = a0;
        *(float4*)(Ah + (size_t)(lr+128)*Sn + k0 + lc) = a1;
        float4 bv4;
        if (tid < 128) {
            int kk  = tid >> 4;
            int seg = (tid & 15) * 4;
            bv4 = *(const float4*)(Vh + (size_t)(k0 + kk)*DKn + seg);
        }
        __syncthreads();
        As[lc+0][lr] = a0.x; As[lc+1][lr] = a0.y;
        As[lc+2][lr] = a0.z; As[lc+3][lr] = a0.w;
        As[lc+0][lr+128] = a1.x; As[lc+1][lr+128] = a1.y;
        As[lc+2][lr+128] = a1.z; As[lc+3][lr+128] = a1.w;
        if (tid < 128) {
            int kk  = tid >> 4;
            int seg = (tid & 15) * 4;
            *(float4*)&Bs[kk][seg] = bv4;
        }
        __syncthreads();
#pragma unroll
        for (int kk = 0; kk < 8; kk++) {
            ulonglong2 a01 = *(const ulonglong2*)&As[kk][ty*8];
            ulonglong2 a23 = *(const ulonglong2*)&As[kk][ty*8+4];
            u64 a2r[4] = {a01.x, a01.y, a23.x, a23.y};
            float4 b0 = *(const float4*)&Bs[kk][tx*8];
            float4 b1 = *(const float4*)&Bs[kk][tx*8+4];
            u64 bb[8] = {pack2(b0.x,b0.x), pack2(b0.y,b0.y), pack2(b0.z,b0.z), pack2(b0.w,b0.w),
                         pack2(b1.x,b1.x), pack2(b1.y,b1.y), pack2(b1.z,b1.z), pack2(b1.w,b1.w)};
#pragma unroll
            for (int i = 0; i < 4; i++)
#pragma unroll
                for (int j = 0; j < 8; j++)
                    acc2[i][j] = ffma2(a2r[i], bb[j], acc2[i][j]);
        }
    }

    float acc[8][8];
#pragma unroll
    for (int i2 = 0; i2 < 4; i2++)
#pragma unroll
        for (int j = 0; j < 8; j++)
            unpack2(acc2[i2][j], acc[2*i2][j], acc[2*i2+1][j]);

#pragma unroll
    for (int i = 0; i < 8; i++) {
        int s = q0 + ty*8 + i;
        float4 v0 = make_float4(acc[i][0], acc[i][1], acc[i][2], acc[i][3]);
        float4 v1 = make_float4(acc[i][4], acc[i][5], acc[i][6], acc[i][7]);
        float* dst = &ctx[((size_t)(b*Sn + s))*Dn + h*DKn + tx*8];
        *(float4*)dst       = v0;
        *(float4*)(dst + 4) = v1;
    }
}

// ---------------------------------------------------------------------------
extern "C" void kernel_launch(void* const* d_in, const int* in_sizes, int n_in,
                              void* d_out, int out_size)
{
    const float* Q   = (const float*)d_in[0];
    const float* Wq  = (const float*)d_in[1];
    const float* bq  = (const float*)d_in[2];
    const float* Wk  = (const float*)d_in[3];
    const float* bk  = (const float*)d_in[4];
    const float* Wv  = (const float*)d_in[5];
    const float* bv  = (const float*)d_in[6];
    const int*   len = (const int*)d_in[7];

    float* ctx = (float*)d_out;
    float* attn;
    if ((size_t)out_size >= (size_t)CTX_ELEMS + ATT_ELEMS) {
        attn = ctx + CTX_ELEMS;   // tuple output: [context | attn]
    } else {
        void* p = nullptr;
        cudaGetSymbolAddress(&p, g_attn_fallback);
        attn = (float*)p;
    }

    // 1) QKV projections (z = 0:q, 1:k, 2:v)
    qkv_kernel<<<dim3(Dn/128, (Bn*Sn)/128, 3), 256>>>(Q, Wq, bq, Wk, bk, Wv, bv);
    // 2) exp(scores)*mask + fused row partial sums
    scores_kernel<<<dim3(Sn/128, Sn/128, BH), 256>>>(len, attn);
    // 3) finish rowsums
    rowsum_reduce_kernel<<<dim3((BH*Sn + 255)/256), 256>>>();
    // 4) context = normalized attn @ V (normalizes attn in place)
    av_kernel<<<dim3(Sn/256, BH), 256>>>(attn, ctx);
}

// round 4
// speedup vs baseline: 1.6478x; 1.4940x over previous
#include <cuda_runtime.h>
#include <cuda_bf16.h>
#include <math.h>
#include <stdint.h>

#define Bn   32
#define Sn   512
#define Dn   1024
#define Hn   16
#define DKn  64
#define BH   (Bn*Hn)                 // 512
#define Mtot (Bn*Sn)                 // 16384
#define CTX_ELEMS (Bn*Sn*Dn)         // 16,777,216
#define ATT_ELEMS ((size_t)Bn*Hn*Sn*Sn) // 134,217,728

// Scratch (allocation-free per harness rules)
__device__ float g_q[CTX_ELEMS];
__device__ float g_k[CTX_ELEMS];
__device__ float g_v[CTX_ELEMS];
__device__ float g_rowsum[BH*Sn];
__device__ float g_part[(size_t)BH*Sn*4];
__device__ float g_attn_fallback[ATT_ELEMS];
// bf16 hi/lo splits
__device__ __nv_bfloat16 g_xb0[CTX_ELEMS];
__device__ __nv_bfloat16 g_xb1[CTX_ELEMS];
__device__ __nv_bfloat16 g_wb0[3*Dn*Dn];
__device__ __nv_bfloat16 g_wb1[3*Dn*Dn];

typedef unsigned long long u64;

// ---------------- packed fp32x2 (for scores/av kernels) --------------------
__device__ __forceinline__ u64 pack2(float x, float y) {
    u64 r; asm("mov.b64 %0,{%1,%2};" : "=l"(r) : "f"(x), "f"(y)); return r;
}
__device__ __forceinline__ void unpack2(u64 v, float& x, float& y) {
    asm("mov.b64 {%0,%1},%2;" : "=f"(x), "=f"(y) : "l"(v));
}
__device__ __forceinline__ u64 ffma2(u64 a, u64 b, u64 c) {
    u64 d; asm("fma.rn.f32x2 %0,%1,%2,%3;" : "=l"(d) : "l"(a), "l"(b), "l"(c)); return d;
}

// ---------------- mma.sync bf16 (non-'a' tensor path, works on sm_103) -----
__device__ __forceinline__ void mma_bf16(float4& d, const uint32_t* a,
                                         uint32_t b0, uint32_t b1) {
    asm volatile(
        "mma.sync.aligned.m16n8k16.row.col.f32.bf16.bf16.f32 "
        "{%0,%1,%2,%3},{%4,%5,%6,%7},{%8,%9},{%0,%1,%2,%3};"
        : "+f"(d.x), "+f"(d.y), "+f"(d.z), "+f"(d.w)
        : "r"(a[0]), "r"(a[1]), "r"(a[2]), "r"(a[3]), "r"(b0), "r"(b1));
}

// ---------------------------------------------------------------------------
// prep: bf16 hi/lo splits of X and the 3 weight matrices
// ---------------------------------------------------------------------------
__global__ __launch_bounds__(256) void prep_x_kernel(const float* __restrict__ X)
{
    size_t i = (size_t)blockIdx.x * 256 + threadIdx.x;   // float4 index
    float4 v = ((const float4*)X)[i];
    float f[4] = {v.x, v.y, v.z, v.w};
    __nv_bfloat16 b0[4], b1[4];
#pragma unroll
    for (int k = 0; k < 4; k++) {
        b0[k] = __float2bfloat16(f[k]);
        b1[k] = __float2bfloat16(f[k] - __bfloat162float(b0[k]));
    }
    *(__nv_bfloat162*)&g_xb0[i*4]     = __nv_bfloat162(b0[0], b0[1]);
    *(__nv_bfloat162*)&g_xb0[i*4 + 2] = __nv_bfloat162(b0[2], b0[3]);
    *(__nv_bfloat162*)&g_xb1[i*4]     = __nv_bfloat162(b1[0], b1[1]);
    *(__nv_bfloat162*)&g_xb1[i*4 + 2] = __nv_bfloat162(b1[2], b1[3]);
}

__global__ __launch_bounds__(256) void prep_w_kernel(
    const float* __restrict__ Wq, const float* __restrict__ Wk, const float* __restrict__ Wv)
{
    size_t i = (size_t)blockIdx.x * 256 + threadIdx.x;   // float4 index
    int z = (int)(i >> 18);                              // 262144 float4 per matrix
    const float* src = (z == 0) ? Wq : (z == 1) ? Wk : Wv;
    float4 v = ((const float4*)src)[i & 262143];
    float f[4] = {v.x, v.y, v.z, v.w};
    __nv_bfloat16 b0[4], b1[4];
#pragma unroll
    for (int k = 0; k < 4; k++) {
        b0[k] = __float2bfloat16(f[k]);
        b1[k] = __float2bfloat16(f[k] - __bfloat162float(b0[k]));
    }
    *(__nv_bfloat162*)&g_wb0[i*4]     = __nv_bfloat162(b0[0], b0[1]);
    *(__nv_bfloat162*)&g_wb0[i*4 + 2] = __nv_bfloat162(b0[2], b0[3]);
    *(__nv_bfloat162*)&g_wb1[i*4]     = __nv_bfloat162(b1[0], b1[1]);
    *(__nv_bfloat162*)&g_wb1[i*4 + 2] = __nv_bfloat162(b1[2], b1[3]);
}

// ---------------------------------------------------------------------------
// QKV projection via mma.sync bf16x3: C = X @ W^T + bias
// CTA tile 128x128, warp tile 32x64, K chunks of 32, 96 chunks total
// (3 split-products x 32). Double-buffered smem, 1 barrier per chunk.
// smem layout: rows of 32 bf16 (16 words) padded to stride 20 words —
// fragment loads hit all 32 banks (20*gid + tig pattern).
// ---------------------------------------------------------------------------
#define SA 20   // smem row stride in words

__global__ __launch_bounds__(256, 2) void qkv_mma_kernel(
    const float* __restrict__ bq, const float* __restrict__ bk, const float* __restrict__ bv)
{
    __shared__ uint32_t As[2][128*SA];
    __shared__ uint32_t Bs[2][128*SA];

    const int tid  = threadIdx.x;
    const int wid  = tid >> 5;
    const int lane = tid & 31;
    const int gid  = lane >> 2;
    const int tig  = lane & 3;
    const int wm   = wid >> 1;       // 0..3 (M)
    const int wn   = wid & 1;        // 0..1 (N)
    const int z    = blockIdx.z;
    const int bm   = blockIdx.y * 128;
    const int bn   = blockIdx.x * 128;
    const size_t zoff = (size_t)z * Dn * Dn;

    const __nv_bfloat16* w0p = g_wb0 + zoff;
    const __nv_bfloat16* w1p = g_wb1 + zoff;

    const int r0 = tid >> 3;         // staging row base (0..31)
    const int c4 = tid & 7;          // staging 4-bf16 chunk

    float4 acc[2][8];
#pragma unroll
    for (int mt = 0; mt < 2; mt++)
#pragma unroll
        for (int nt = 0; nt < 8; nt++) acc[mt][nt] = make_float4(0.f, 0.f, 0.f, 0.f);

    uint2 areg[4], breg[4];

    // preload chunk 0 (product 0: xb0 * wb0, k0 = 0)
    {
        const __nv_bfloat16* a = g_xb0 + (size_t)bm * Dn;
        const __nv_bfloat16* w = w0p   + (size_t)bn * Dn;
#pragma unroll
        for (int j = 0; j < 4; j++) {
            int row = r0 + j*32;
            areg[j] = *(const uint2*)(a + (size_t)row*Dn + c4*4);
            breg[j] = *(const uint2*)(w + (size_t)row*Dn + c4*4);
        }
#pragma unroll
        for (int j = 0; j < 4; j++) {
            int row = r0 + j*32;
            int wo = row*SA + c4*2;
            *(uint2*)&As[0][wo] = areg[j];
            *(uint2*)&Bs[0][wo] = breg[j];
        }
    }
    __syncthreads();

    for (int it = 0; it < 96; it++) {
        const int cur = it & 1;
        if (it + 1 < 96) {
            int p  = (it + 1) >> 5;
            int kc = ((it + 1) & 31) * 32;
            const __nv_bfloat16* a = ((p == 2) ? g_xb1 : g_xb0) + (size_t)bm * Dn + kc;
            const __nv_bfloat16* w = ((p == 1) ? w1p  : w0p  ) + (size_t)bn * Dn + kc;
#pragma unroll
            for (int j = 0; j < 4; j++) {
                int row = r0 + j*32;
                areg[j] = *(const uint2*)(a + (size_t)row*Dn + c4*4);
                breg[j] = *(const uint2*)(w + (size_t)row*Dn + c4*4);
            }
        }
        // compute 2 x k16 steps on current buffer
#pragma unroll
        for (int s = 0; s < 2; s++) {
            uint32_t af[2][4];
#pragma unroll
            for (int mt = 0; mt < 2; mt++) {
                int base = (wm*32 + mt*16 + gid)*SA + s*8 + tig;
                af[mt][0] = As[cur][base];
                af[mt][1] = As[cur][base + 8*SA];
                af[mt][2] = As[cur][base + 4];
                af[mt][3] = As[cur][base + 8*SA + 4];
            }
#pragma unroll
            for (int nt = 0; nt < 8; nt++) {
                int nb = (wn*64 + nt*8 + gid)*SA + s*8 + tig;
                uint32_t b0 = Bs[cur][nb];
                uint32_t b1 = Bs[cur][nb + 4];
                mma_bf16(acc[0][nt], af[0], b0, b1);
                mma_bf16(acc[1][nt], af[1], b0, b1);
            }
        }
        if (it + 1 < 96) {
            const int nxt = (it + 1) & 1;
#pragma unroll
            for (int j = 0; j < 4; j++) {
                int row = r0 + j*32;
                int wo = row*SA + c4*2;
                *(uint2*)&As[nxt][wo] = areg[j];
                *(uint2*)&Bs[nxt][wo] = breg[j];
            }
            __syncthreads();
        }
    }

    // epilogue: add bias, store [B,H,S,DK]
    const float* bias = (z == 0) ? bq : (z == 1) ? bk : bv;
    float* out = (z == 0) ? g_q : (z == 1) ? g_k : g_v;
#pragma unroll
    for (int mt = 0; mt < 2; mt++) {
        int rowa = bm + wm*32 + mt*16 + gid;
        int rowb = rowa + 8;
        int ba = rowa >> 9, sa = rowa & 511;
        int bb2 = rowb >> 9, sb = rowb & 511;
#pragma unroll
        for (int nt = 0; nt < 8; nt++) {
            int feat = bn + wn*64 + nt*8 + tig*2;
            int h = feat >> 6, dk = feat & 63;
            float2 bv2 = *(const float2*)&bias[feat];
            float2 v0 = make_float2(acc[mt][nt].x + bv2.x, acc[mt][nt].y + bv2.y);
            float2 v1 = make_float2(acc[mt][nt].z + bv2.x, acc[mt][nt].w + bv2.y);
            *(float2*)&out[((size_t)((ba *Hn + h)*Sn + sa))*DKn + dk] = v0;
            *(float2*)&out[((size_t)((bb2*Hn + h)*Sn + sb))*DKn + dk] = v1;
        }
    }
}

// ---------------------------------------------------------------------------
// Kernel 2: E[bh,q,k] = exp(q·k / 8) * (k < length[b]); fused row partials
// ---------------------------------------------------------------------------
__global__ __launch_bounds__(256, 2) void scores_kernel(
    const int* __restrict__ length, float* __restrict__ attn)
{
    const int bh = blockIdx.z;
    const int b  = bh >> 4;
    const int q0 = blockIdx.y * 128;
    const int k0 = blockIdx.x * 128;
    const float* Qh = g_q + (size_t)bh * Sn * DKn;
    const float* Kh = g_k + (size_t)bh * Sn * DKn;

    __shared__ __align__(16) float As[8][132];
    __shared__ __align__(16) float Bs[8][132];

    const int tid = threadIdx.x;
    const int tx = tid & 15;
    const int ty = tid >> 4;
    const int lr = tid >> 1;
    const int lc = (tid & 1) * 4;

    const float* aptr = Qh + (size_t)(q0 + lr) * DKn + lc;
    const float* bptr = Kh + (size_t)(k0 + lr) * DKn + lc;

    u64 acc2[4][8];
#pragma unroll
    for (int i = 0; i < 4; i++)
#pragma unroll
        for (int j = 0; j < 8; j++) acc2[i][j] = 0ull;

#pragma unroll
    for (int d0 = 0; d0 < DKn; d0 += 8) {
        float4 av  = *(const float4*)(aptr + d0);
        float4 bv4 = *(const float4*)(bptr + d0);
        __syncthreads();
        As[lc+0][lr] = av.x;  As[lc+1][lr] = av.y;
        As[lc+2][lr] = av.z;  As[lc+3][lr] = av.w;
        Bs[lc+0][lr] = bv4.x; Bs[lc+1][lr] = bv4.y;
        Bs[lc+2][lr] = bv4.z; Bs[lc+3][lr] = bv4.w;
        __syncthreads();
#pragma unroll
        for (int kk = 0; kk < 8; kk++) {
            ulonglong2 a01 = *(const ulonglong2*)&As[kk][ty*8];
            ulonglong2 a23 = *(const ulonglong2*)&As[kk][ty*8+4];
            u64 a2r[4] = {a01.x, a01.y, a23.x, a23.y};
            float4 b0 = *(const float4*)&Bs[kk][tx*8];
            float4 b1 = *(const float4*)&Bs[kk][tx*8+4];
            u64 bb[8] = {pack2(b0.x,b0.x), pack2(b0.y,b0.y), pack2(b0.z,b0.z), pack2(b0.w,b0.w),
                         pack2(b1.x,b1.x), pack2(b1.y,b1.y), pack2(b1.z,b1.z), pack2(b1.w,b1.w)};
#pragma unroll
            for (int i = 0; i < 4; i++)
#pragma unroll
                for (int j = 0; j < 8; j++)
                    acc2[i][j] = ffma2(a2r[i], bb[j], acc2[i][j]);
        }
    }

    float acc[8][8];
#pragma unroll
    for (int i2 = 0; i2 < 4; i2++)
#pragma unroll
        for (int j = 0; j < 8; j++)
            unpack2(acc2[i2][j], acc[2*i2][j], acc[2*i2+1][j]);

    const int len = length[b];
#pragma unroll
    for (int i = 0; i < 8; i++) {
        int q = q0 + ty*8 + i;
        float e[8];
        float rp = 0.0f;
#pragma unroll
        for (int j = 0; j < 8; j++) {
            int kcol = k0 + tx*8 + j;
            e[j] = (kcol < len) ? expf(acc[i][j] * 0.125f) : 0.0f;
            rp += e[j];
        }
        float4 v0 = make_float4(e[0], e[1], e[2], e[3]);
        float4 v1 = make_float4(e[4], e[5], e[6], e[7]);
        float* dst = &attn[((size_t)bh*Sn + q)*Sn + k0 + tx*8];
        *(float4*)dst       = v0;
        *(float4*)(dst + 4) = v1;
        rp += __shfl_xor_sync(0xffffffffu, rp, 8);
        rp += __shfl_xor_sync(0xffffffffu, rp, 4);
        rp += __shfl_xor_sync(0xffffffffu, rp, 2);
        rp += __shfl_xor_sync(0xffffffffu, rp, 1);
        if (tx == 0)
            g_part[((size_t)bh*Sn + q)*4 + blockIdx.x] = rp;
    }
}

// ---------------------------------------------------------------------------
__global__ __launch_bounds__(256) void rowsum_reduce_kernel()
{
    int r = blockIdx.x * 256 + threadIdx.x;
    if (r < BH*Sn) {
        float4 p = *(const float4*)&g_part[(size_t)r*4];
        g_rowsum[r] = p.x + p.y + p.z + p.w;
    }
}

// ---------------------------------------------------------------------------
// Kernel 4: context = (E * inv) @ V, fused normalize (writes attn in place)
// ---------------------------------------------------------------------------
__global__ __launch_bounds__(256, 2) void av_kernel(
    float* __restrict__ attn, float* __restrict__ ctx)
{
    const int bh = blockIdx.y;
    const int b  = bh >> 4;
    const int h  = bh & 15;
    const int q0 = blockIdx.x * 256;
    float* Ah = attn + ((size_t)bh*Sn + q0) * Sn;
    const float* Vh = g_v + (size_t)bh * Sn * DKn;

    __shared__ __align__(16) float As[8][264];
    __shared__ __align__(16) float Bs[8][68];
    __shared__ float invS[256];

    const int tid = threadIdx.x;
    const int tx = tid & 7;
    const int ty = tid >> 3;
    const int lr = tid >> 1;
    const int lc = (tid & 1) * 4;

    invS[tid] = 1.0f / (g_rowsum[(size_t)bh*Sn + q0 + tid] + 1e-8f);
    __syncthreads();
    const float inv0 = invS[lr];
    const float inv1 = invS[lr + 128];

    u64 acc2[4][8];
#pragma unroll
    for (int i = 0; i < 4; i++)
#pragma unroll
        for (int j = 0; j < 8; j++) acc2[i][j] = 0ull;

    for (int k0 = 0; k0 < Sn; k0 += 8) {
        float4 a0 = *(const float4*)(Ah + (size_t)lr       *Sn + k0 + lc);
        float4 a1 = *(const float4*)(Ah + (size_t)(lr+128) *Sn + k0 + lc);
        a0.x *= inv0; a0.y *= inv0; a0.z *= inv0; a0.w *= inv0;
        a1.x *= inv1; a1.y *= inv1; a1.z *= inv1; a1.w *= inv1;
        *(float4*)(Ah + (size_t)lr      *Sn + k0 + lc) = a0;
        *(float4*)(Ah + (size_t)(lr+128)*Sn + k0 + lc) = a1;
        float4 bv4;
        if (tid < 128) {
            int kk  = tid >> 4;
            int seg = (tid & 15) * 4;
            bv4 = *(const float4*)(Vh + (size_t)(k0 + kk)*DKn + seg);
        }
        __syncthreads();
        As[lc+0][lr] = a0.x; As[lc+1][lr] = a0.y;
        As[lc+2][lr] = a0.z; As[lc+3][lr] = a0.w;
        As[lc+0][lr+128] = a1.x; As[lc+1][lr+128] = a1.y;
        As[lc+2][lr+128] = a1.z; As[lc+3][lr+128] = a1.w;
        if (tid < 128) {
            int kk  = tid >> 4;
            int seg = (tid & 15) * 4;
            *(float4*)&Bs[kk][seg] = bv4;
        }
        __syncthreads();
#pragma unroll
        for (int kk = 0; kk < 8; kk++) {
            ulonglong2 a01 = *(const ulonglong2*)&As[kk][ty*8];
            ulonglong2 a23 = *(const ulonglong2*)&As[kk][ty*8+4];
            u64 a2r[4] = {a01.x, a01.y, a23.x, a23.y};
            float4 b0 = *(const float4*)&Bs[kk][tx*8];
            float4 b1 = *(const float4*)&Bs[kk][tx*8+4];
            u64 bb[8] = {pack2(b0.x,b0.x), pack2(b0.y,b0.y), pack2(b0.z,b0.z), pack2(b0.w,b0.w),
                         pack2(b1.x,b1.x), pack2(b1.y,b1.y), pack2(b1.z,b1.z), pack2(b1.w,b1.w)};
#pragma unroll
            for (int i = 0; i < 4; i++)
#pragma unroll
                for (int j = 0; j < 8; j++)
                    acc2[i][j] = ffma2(a2r[i], bb[j], acc2[i][j]);
        }
        __syncthreads();
    }

    float acc[8][8];
#pragma unroll
    for (int i2 = 0; i2 < 4; i2++)
#pragma unroll
        for (int j = 0; j < 8; j++)
            unpack2(acc2[i2][j], acc[2*i2][j], acc[2*i2+1][j]);

#pragma unroll
    for (int i = 0; i < 8; i++) {
        int s = q0 + ty*8 + i;
        float4 v0 = make_float4(acc[i][0], acc[i][1], acc[i][2], acc[i][3]);
        float4 v1 = make_float4(acc[i][4], acc[i][5], acc[i][6], acc[i][7]);
        float* dst = &ctx[((size_t)(b*Sn + s))*Dn + h*DKn + tx*8];
        *(float4*)dst       = v0;
        *(float4*)(dst + 4) = v1;
    }
}

// ---------------------------------------------------------------------------
extern "C" void kernel_launch(void* const* d_in, const int* in_sizes, int n_in,
                              void* d_out, int out_size)
{
    const float* Q   = (const float*)d_in[0];
    const float* Wq  = (const float*)d_in[1];
    const float* bq  = (const float*)d_in[2];
    const float* Wk  = (const float*)d_in[3];
    const float* bk  = (const float*)d_in[4];
    const float* Wv  = (const float*)d_in[5];
    const float* bv  = (const float*)d_in[6];
    const int*   len = (const int*)d_in[7];

    float* ctx = (float*)d_out;
    float* attn;
    if ((size_t)out_size >= (size_t)CTX_ELEMS + ATT_ELEMS) {
        attn = ctx + CTX_ELEMS;   // tuple output: [context | attn]
    } else {
        void* p = nullptr;
        cudaGetSymbolAddress(&p, g_attn_fallback);
        attn = (float*)p;
    }

    // 0) bf16 hi/lo splits
    prep_x_kernel<<<dim3(CTX_ELEMS/4/256), 256>>>(Q);
    prep_w_kernel<<<dim3(3*Dn*Dn/4/256), 256>>>(Wq, Wk, Wv);
    // 1) QKV projections on tensor cores via mma.sync (z = 0:q, 1:k, 2:v)
    qkv_mma_kernel<<<dim3(Dn/128, Mtot/128, 3), 256>>>(bq, bk, bv);
    // 2) exp(scores)*mask + fused row partial sums
    scores_kernel<<<dim3(Sn/128, Sn/128, BH), 256>>>(len, attn);
    // 3) finish rowsums
    rowsum_reduce_kernel<<<dim3((BH*Sn + 255)/256), 256>>>();
    // 4) context = normalized attn @ V (normalizes attn in place)
    av_kernel<<<dim3(Sn/256, BH), 256>>>(attn, ctx);
}

// round 5
// speedup vs baseline: 2.0160x; 1.2235x over previous
#include <cuda_runtime.h>
#include <cuda_bf16.h>
#include <math.h>
#include <stdint.h>

#define Bn   32
#define Sn   512
#define Dn   1024
#define Hn   16
#define DKn  64
#define BH   (Bn*Hn)                 // 512
#define Mtot (Bn*Sn)                 // 16384
#define CTX_ELEMS (Bn*Sn*Dn)         // 16,777,216
#define ATT_ELEMS ((size_t)Bn*Hn*Sn*Sn) // 134,217,728

// Scratch (allocation-free per harness rules)
__device__ float g_v[CTX_ELEMS];
__device__ float g_rowsum[BH*Sn];
__device__ float g_part[(size_t)BH*Sn*8];
__device__ float g_attn_fallback[ATT_ELEMS];
// bf16 hi/lo splits
__device__ __nv_bfloat16 g_xb0[CTX_ELEMS];
__device__ __nv_bfloat16 g_xb1[CTX_ELEMS];
__device__ __nv_bfloat16 g_wb0[3*Dn*Dn];
__device__ __nv_bfloat16 g_wb1[3*Dn*Dn];
__device__ __nv_bfloat16 g_qb0[CTX_ELEMS];
__device__ __nv_bfloat16 g_qb1[CTX_ELEMS];
__device__ __nv_bfloat16 g_kb0[CTX_ELEMS];
__device__ __nv_bfloat16 g_kb1[CTX_ELEMS];
__device__ __nv_bfloat16 g_vt0[CTX_ELEMS];   // V^T: [bh][dk=64][s=512]
__device__ __nv_bfloat16 g_vt1[CTX_ELEMS];

// ---------------- mma.sync bf16 (non-'a' tensor path, works on sm_103) -----
__device__ __forceinline__ void mma_bf16(float4& d, const uint32_t* a,
                                         uint32_t b0, uint32_t b1) {
    asm volatile(
        "mma.sync.aligned.m16n8k16.row.col.f32.bf16.bf16.f32 "
        "{%0,%1,%2,%3},{%4,%5,%6,%7},{%8,%9},{%0,%1,%2,%3};"
        : "+f"(d.x), "+f"(d.y), "+f"(d.z), "+f"(d.w)
        : "r"(a[0]), "r"(a[1]), "r"(a[2]), "r"(a[3]), "r"(b0), "r"(b1));
}

__device__ __forceinline__ void bsplit(float v, __nv_bfloat16& h, __nv_bfloat16& l) {
    h = __float2bfloat16(v);
    l = __float2bfloat16(v - __bfloat162float(h));
}
__device__ __forceinline__ uint32_t packbf(__nv_bfloat16 a, __nv_bfloat16 b) {
    __nv_bfloat162 t(a, b);
    return *(uint32_t*)&t;
}

// ---------------------------------------------------------------------------
// prep: bf16 hi/lo splits of X and the 3 weight matrices
// ---------------------------------------------------------------------------
__global__ __launch_bounds__(256) void prep_x_kernel(const float* __restrict__ X)
{
    size_t i = (size_t)blockIdx.x * 256 + threadIdx.x;
    float4 v = ((const float4*)X)[i];
    float f[4] = {v.x, v.y, v.z, v.w};
    __nv_bfloat16 b0[4], b1[4];
#pragma unroll
    for (int k = 0; k < 4; k++) bsplit(f[k], b0[k], b1[k]);
    ((uint32_t*)g_xb0)[i*2]   = packbf(b0[0], b0[1]);
    ((uint32_t*)g_xb0)[i*2+1] = packbf(b0[2], b0[3]);
    ((uint32_t*)g_xb1)[i*2]   = packbf(b1[0], b1[1]);
    ((uint32_t*)g_xb1)[i*2+1] = packbf(b1[2], b1[3]);
}

__global__ __launch_bounds__(256) void prep_w_kernel(
    const float* __restrict__ Wq, const float* __restrict__ Wk, const float* __restrict__ Wv)
{
    size_t i = (size_t)blockIdx.x * 256 + threadIdx.x;
    int z = (int)(i >> 18);
    const float* src = (z == 0) ? Wq : (z == 1) ? Wk : Wv;
    float4 v = ((const float4*)src)[i & 262143];
    float f[4] = {v.x, v.y, v.z, v.w};
    __nv_bfloat16 b0[4], b1[4];
#pragma unroll
    for (int k = 0; k < 4; k++) bsplit(f[k], b0[k], b1[k]);
    ((uint32_t*)g_wb0)[i*2]   = packbf(b0[0], b0[1]);
    ((uint32_t*)g_wb0)[i*2+1] = packbf(b0[2], b0[3]);
    ((uint32_t*)g_wb1)[i*2]   = packbf(b1[0], b1[1]);
    ((uint32_t*)g_wb1)[i*2+1] = packbf(b1[2], b1[3]);
}

// ---------------------------------------------------------------------------
// QKV projection via mma.sync bf16x3: C = X @ W^T + bias
// CTA 128x128, warp tile 32x64, 96 K-chunks (3 products x 32).
// q/k outputs written as bf16 hi/lo pairs; v as fp32.
// ---------------------------------------------------------------------------
#define SA 20   // smem row stride in words

__global__ __launch_bounds__(256, 2) void qkv_mma_kernel(
    const float* __restrict__ bq, const float* __restrict__ bk, const float* __restrict__ bv)
{
    __shared__ uint32_t As[2][128*SA];
    __shared__ uint32_t Bs[2][128*SA];

    const int tid  = threadIdx.x;
    const int wid  = tid >> 5;
    const int lane = tid & 31;
    const int gid  = lane >> 2;
    const int tig  = lane & 3;
    const int wm   = wid >> 1;
    const int wn   = wid & 1;
    const int z    = blockIdx.z;
    const int bm   = blockIdx.y * 128;
    const int bn   = blockIdx.x * 128;
    const size_t zoff = (size_t)z * Dn * Dn;

    const __nv_bfloat16* w0p = g_wb0 + zoff;
    const __nv_bfloat16* w1p = g_wb1 + zoff;

    const int r0 = tid >> 3;
    const int c4 = tid & 7;

    float4 acc[2][8];
#pragma unroll
    for (int mt = 0; mt < 2; mt++)
#pragma unroll
        for (int nt = 0; nt < 8; nt++) acc[mt][nt] = make_float4(0.f, 0.f, 0.f, 0.f);

    uint2 areg[4], breg[4];
    {
        const __nv_bfloat16* a = g_xb0 + (size_t)bm * Dn;
        const __nv_bfloat16* w = w0p   + (size_t)bn * Dn;
#pragma unroll
        for (int j = 0; j < 4; j++) {
            int row = r0 + j*32;
            areg[j] = *(const uint2*)(a + (size_t)row*Dn + c4*4);
            breg[j] = *(const uint2*)(w + (size_t)row*Dn + c4*4);
        }
#pragma unroll
        for (int j = 0; j < 4; j++) {
            int row = r0 + j*32;
            int wo = row*SA + c4*2;
            *(uint2*)&As[0][wo] = areg[j];
            *(uint2*)&Bs[0][wo] = breg[j];
        }
    }
    __syncthreads();

    for (int it = 0; it < 96; it++) {
        const int cur = it & 1;
        if (it + 1 < 96) {
            int p  = (it + 1) >> 5;
            int kc = ((it + 1) & 31) * 32;
            const __nv_bfloat16* a = ((p == 2) ? g_xb1 : g_xb0) + (size_t)bm * Dn + kc;
            const __nv_bfloat16* w = ((p == 1) ? w1p  : w0p  ) + (size_t)bn * Dn + kc;
#pragma unroll
            for (int j = 0; j < 4; j++) {
                int row = r0 + j*32;
                areg[j] = *(const uint2*)(a + (size_t)row*Dn + c4*4);
                breg[j] = *(const uint2*)(w + (size_t)row*Dn + c4*4);
            }
        }
#pragma unroll
        for (int s = 0; s < 2; s++) {
            uint32_t af[2][4];
#pragma unroll
            for (int mt = 0; mt < 2; mt++) {
                int base = (wm*32 + mt*16 + gid)*SA + s*8 + tig;
                af[mt][0] = As[cur][base];
                af[mt][1] = As[cur][base + 8*SA];
                af[mt][2] = As[cur][base + 4];
                af[mt][3] = As[cur][base + 8*SA + 4];
            }
#pragma unroll
            for (int nt = 0; nt < 8; nt++) {
                int nb = (wn*64 + nt*8 + gid)*SA + s*8 + tig;
                uint32_t b0 = Bs[cur][nb];
                uint32_t b1 = Bs[cur][nb + 4];
                mma_bf16(acc[0][nt], af[0], b0, b1);
                mma_bf16(acc[1][nt], af[1], b0, b1);
            }
        }
        if (it + 1 < 96) {
            const int nxt = (it + 1) & 1;
#pragma unroll
            for (int j = 0; j < 4; j++) {
                int row = r0 + j*32;
                int wo = row*SA + c4*2;
                *(uint2*)&As[nxt][wo] = areg[j];
                *(uint2*)&Bs[nxt][wo] = breg[j];
            }
            __syncthreads();
        }
    }

    const float* bias = (z == 0) ? bq : (z == 1) ? bk : bv;
    if (z == 2) {
        // V: fp32 [bh][s][dk]
#pragma unroll
        for (int mt = 0; mt < 2; mt++) {
            int rowa = bm + wm*32 + mt*16 + gid;
            int rowb = rowa + 8;
            int ba = rowa >> 9, sa = rowa & 511;
            int bb2 = rowb >> 9, sb = rowb & 511;
#pragma unroll
            for (int nt = 0; nt < 8; nt++) {
                int feat = bn + wn*64 + nt*8 + tig*2;
                int h = feat >> 6, dk = feat & 63;
                float2 bv2 = *(const float2*)&bias[feat];
                float2 v0 = make_float2(acc[mt][nt].x + bv2.x, acc[mt][nt].y + bv2.y);
                float2 v1 = make_float2(acc[mt][nt].z + bv2.x, acc[mt][nt].w + bv2.y);
                *(float2*)&g_v[((size_t)((ba *Hn + h)*Sn + sa))*DKn + dk] = v0;
                *(float2*)&g_v[((size_t)((bb2*Hn + h)*Sn + sb))*DKn + dk] = v1;
            }
        }
    } else {
        // Q/K: bf16 hi/lo pairs [bh][s][dk]
        __nv_bfloat16* o0 = (z == 0) ? g_qb0 : g_kb0;
        __nv_bfloat16* o1 = (z == 0) ? g_qb1 : g_kb1;
#pragma unroll
        for (int mt = 0; mt < 2; mt++) {
            int rowa = bm + wm*32 + mt*16 + gid;
            int rowb = rowa + 8;
            int ba = rowa >> 9, sa = rowa & 511;
            int bb2 = rowb >> 9, sb = rowb & 511;
#pragma unroll
            for (int nt = 0; nt < 8; nt++) {
                int feat = bn + wn*64 + nt*8 + tig*2;
                int h = feat >> 6, dk = feat & 63;
                float2 bv2 = *(const float2*)&bias[feat];
                float vx = acc[mt][nt].x + bv2.x, vy = acc[mt][nt].y + bv2.y;
                float vz = acc[mt][nt].z + bv2.x, vw = acc[mt][nt].w + bv2.y;
                __nv_bfloat16 hx,lx,hy,ly,hz,lz,hw,lw;
                bsplit(vx,hx,lx); bsplit(vy,hy,ly); bsplit(vz,hz,lz); bsplit(vw,hw,lw);
                size_t ia = ((size_t)((ba *Hn + h)*Sn + sa))*DKn + dk;
                size_t ib = ((size_t)((bb2*Hn + h)*Sn + sb))*DKn + dk;
                *(uint32_t*)&o0[ia] = packbf(hx,hy);
                *(uint32_t*)&o1[ia] = packbf(lx,ly);
                *(uint32_t*)&o0[ib] = packbf(hz,hw);
                *(uint32_t*)&o1[ib] = packbf(lz,lw);
            }
        }
    }
}

// ---------------------------------------------------------------------------
// vtrans: g_v fp32 [bh][s][64] -> bf16 hi/lo V^T [bh][64][512]
// ---------------------------------------------------------------------------
__global__ __launch_bounds__(256) void vtrans_kernel()
{
    const int bh = blockIdx.y;
    const int s0 = blockIdx.x * 64;
    __shared__ float T[64][65];
    const int tid = threadIdx.x;
#pragma unroll
    for (int j = 0; j < 4; j++) {
        int f = tid + j*256;         // 1024 float4
        int row = f >> 4, cc = (f & 15) * 4;
        float4 v = *(const float4*)&g_v[((size_t)bh*Sn + s0 + row)*DKn + cc];
        T[row][cc] = v.x; T[row][cc+1] = v.y; T[row][cc+2] = v.z; T[row][cc+3] = v.w;
    }
    __syncthreads();
#pragma unroll
    for (int j = 0; j < 8; j++) {
        int g = tid + j*256;         // 2048 bf16x2 sites
        int dk = g >> 5, sc = (g & 31) * 2;
        float va = T[sc][dk], vb = T[sc+1][dk];
        __nv_bfloat16 ha,la,hb,lb;
        bsplit(va,ha,la); bsplit(vb,hb,lb);
        size_t idx = ((size_t)bh*DKn + dk)*Sn + s0 + sc;
        *(uint32_t*)&g_vt0[idx] = packbf(ha,hb);
        *(uint32_t*)&g_vt1[idx] = packbf(la,lb);
    }
}

// ---------------------------------------------------------------------------
// scores via mma: E[q][k] = exp((q·k)/8)*mask, 128x128 tile per block,
// 6 K-chunks (3 products x 2 chunks of 32 over DK=64). Fused row partials.
// ---------------------------------------------------------------------------
__global__ __launch_bounds__(256, 2) void scores_mma_kernel(
    const int* __restrict__ length, float* __restrict__ attn)
{
    __shared__ uint32_t As[2][128*SA];
    __shared__ uint32_t Bs[2][128*SA];

    const int tid  = threadIdx.x;
    const int wid  = tid >> 5;
    const int lane = tid & 31;
    const int gid  = lane >> 2;
    const int tig  = lane & 3;
    const int wm   = wid >> 1;
    const int wn   = wid & 1;
    const int bh = blockIdx.z;
    const int b  = bh >> 4;
    const int q0 = blockIdx.y * 128;
    const int k0 = blockIdx.x * 128;

    const int r0 = tid >> 3;
    const int c4 = tid & 7;

    const __nv_bfloat16* qs[2] = { g_qb0 + ((size_t)bh*Sn + q0)*DKn,
                                   g_qb1 + ((size_t)bh*Sn + q0)*DKn };
    const __nv_bfloat16* ks[2] = { g_kb0 + ((size_t)bh*Sn + k0)*DKn,
                                   g_kb1 + ((size_t)bh*Sn + k0)*DKn };
    const int pa[3] = {0, 0, 1};
    const int pb[3] = {0, 1, 0};

    float4 acc[2][8];
#pragma unroll
    for (int mt = 0; mt < 2; mt++)
#pragma unroll
        for (int nt = 0; nt < 8; nt++) acc[mt][nt] = make_float4(0.f, 0.f, 0.f, 0.f);

    uint2 areg[4], breg[4];
    {
#pragma unroll
        for (int j = 0; j < 4; j++) {
            int row = r0 + j*32;
            areg[j] = *(const uint2*)(qs[0] + (size_t)row*DKn + c4*4);
            breg[j] = *(const uint2*)(ks[0] + (size_t)row*DKn + c4*4);
        }
#pragma unroll
        for (int j = 0; j < 4; j++) {
            int row = r0 + j*32;
            int wo = row*SA + c4*2;
            *(uint2*)&As[0][wo] = areg[j];
            *(uint2*)&Bs[0][wo] = breg[j];
        }
    }
    __syncthreads();

    for (int it = 0; it < 6; it++) {
        const int cur = it & 1;
        if (it + 1 < 6) {
            int p  = (it + 1) >> 1;
            int kc = ((it + 1) & 1) * 32;
            const __nv_bfloat16* a = qs[pa[p]] + kc;
            const __nv_bfloat16* w = ks[pb[p]] + kc;
#pragma unroll
            for (int j = 0; j < 4; j++) {
                int row = r0 + j*32;
                areg[j] = *(const uint2*)(a + (size_t)row*DKn + c4*4);
                breg[j] = *(const uint2*)(w + (size_t)row*DKn + c4*4);
            }
        }
#pragma unroll
        for (int s = 0; s < 2; s++) {
            uint32_t af[2][4];
#pragma unroll
            for (int mt = 0; mt < 2; mt++) {
                int base = (wm*32 + mt*16 + gid)*SA + s*8 + tig;
                af[mt][0] = As[cur][base];
                af[mt][1] = As[cur][base + 8*SA];
                af[mt][2] = As[cur][base + 4];
                af[mt][3] = As[cur][base + 8*SA + 4];
            }
#pragma unroll
            for (int nt = 0; nt < 8; nt++) {
                int nb = (wn*64 + nt*8 + gid)*SA + s*8 + tig;
                uint32_t b0 = Bs[cur][nb];
                uint32_t b1 = Bs[cur][nb + 4];
                mma_bf16(acc[0][nt], af[0], b0, b1);
                mma_bf16(acc[1][nt], af[1], b0, b1);
            }
        }
        if (it + 1 < 6) {
            const int nxt = (it + 1) & 1;
#pragma unroll
            for (int j = 0; j < 4; j++) {
                int row = r0 + j*32;
                int wo = row*SA + c4*2;
                *(uint2*)&As[nxt][wo] = areg[j];
                *(uint2*)&Bs[nxt][wo] = breg[j];
            }
            __syncthreads();
        }
    }

    // epilogue: exp + mask + write + row partials
    const int len = length[b];
#pragma unroll
    for (int mt = 0; mt < 2; mt++) {
        int sa = q0 + wm*32 + mt*16 + gid;
        int sb = sa + 8;
        float rpa = 0.f, rpb = 0.f;
#pragma unroll
        for (int nt = 0; nt < 8; nt++) {
            int kc0 = k0 + wn*64 + nt*8 + tig*2;
            float4 a = acc[mt][nt];
            float ex = (kc0   < len) ? expf(a.x * 0.125f) : 0.f;
            float ey = (kc0+1 < len) ? expf(a.y * 0.125f) : 0.f;
            float ez = (kc0   < len) ? expf(a.z * 0.125f) : 0.f;
            float ew = (kc0+1 < len) ? expf(a.w * 0.125f) : 0.f;
            *(float2*)&attn[((size_t)bh*Sn + sa)*Sn + kc0] = make_float2(ex, ey);
            *(float2*)&attn[((size_t)bh*Sn + sb)*Sn + kc0] = make_float2(ez, ew);
            rpa += ex + ey;
            rpb += ez + ew;
        }
        rpa += __shfl_xor_sync(0xffffffffu, rpa, 1);
        rpa += __shfl_xor_sync(0xffffffffu, rpa, 2);
        rpb += __shfl_xor_sync(0xffffffffu, rpb, 1);
        rpb += __shfl_xor_sync(0xffffffffu, rpb, 2);
        if (tig == 0) {
            g_part[((size_t)bh*Sn + sa)*8 + blockIdx.x*2 + wn] = rpa;
            g_part[((size_t)bh*Sn + sb)*8 + blockIdx.x*2 + wn] = rpb;
        }
    }
}

// ---------------------------------------------------------------------------
__global__ __launch_bounds__(256) void rowsum_reduce_kernel()
{
    int r = blockIdx.x * 256 + threadIdx.x;
    if (r < BH*Sn) {
        float4 p0 = ((const float4*)g_part)[r*2];
        float4 p1 = ((const float4*)g_part)[r*2 + 1];
        g_rowsum[r] = p0.x + p0.y + p0.z + p0.w + p1.x + p1.y + p1.z + p1.w;
    }
}

// ---------------------------------------------------------------------------
// av via mma: ctx = (E*inv) @ V. M=128 q, N=64 dk, K=512.
// Reads attn fp32, normalizes + writes back, bf16-splits in-kernel.
// ---------------------------------------------------------------------------
__global__ __launch_bounds__(256, 2) void av_mma_kernel(
    float* __restrict__ attn, float* __restrict__ ctx)
{
    __shared__ uint32_t As0[128*SA];
    __shared__ uint32_t As1[128*SA];
    __shared__ uint32_t Bs0[64*SA];
    __shared__ uint32_t Bs1[64*SA];
    __shared__ float invS[128];

    const int tid  = threadIdx.x;
    const int wid  = tid >> 5;        // warp = wm (8 warps x 16 q-rows)
    const int lane = tid & 31;
    const int gid  = lane >> 2;
    const int tig  = lane & 3;
    const int bh = blockIdx.y;
    const int b  = bh >> 4;
    const int h  = bh & 15;
    const int q0 = blockIdx.x * 128;

    float* Ah = attn + ((size_t)bh*Sn + q0) * Sn;
    const __nv_bfloat16* vt0 = g_vt0 + (size_t)bh * DKn * Sn;
    const __nv_bfloat16* vt1 = g_vt1 + (size_t)bh * DKn * Sn;

    if (tid < 128)
        invS[tid] = 1.0f / (g_rowsum[(size_t)bh*Sn + q0 + tid] + 1e-8f);

    float4 acc[8];
#pragma unroll
    for (int nt = 0; nt < 8; nt++) acc[nt] = make_float4(0.f, 0.f, 0.f, 0.f);

    const int r0 = tid >> 3;
    const int c4 = tid & 7;

    for (int kc = 0; kc < Sn; kc += 32) {
        // load attn fp32, scale, write back, split
        float4 av[4];
        float iv[4];
#pragma unroll
        for (int j = 0; j < 4; j++) {
            int f = tid + j*256;
            int row = f >> 3, cc = f & 7;
            av[j] = *(const float4*)(Ah + (size_t)row*Sn + kc + cc*4);
        }
        uint2 bv0[2], bv1[2];
#pragma unroll
        for (int j = 0; j < 2; j++) {
            int g = tid + j*256;
            int row = g >> 3, cc = g & 7;
            bv0[j] = *(const uint2*)(vt0 + (size_t)row*Sn + kc + cc*4);
            bv1[j] = *(const uint2*)(vt1 + (size_t)row*Sn + kc + cc*4);
        }
        __syncthreads();   // previous chunk's mma done; invS ready (first iter)
#pragma unroll
        for (int j = 0; j < 4; j++) {
            int f = tid + j*256;
            int row = f >> 3, cc = f & 7;
            iv[j] = invS[row];
            float4 vv = av[j];
            vv.x *= iv[j]; vv.y *= iv[j]; vv.z *= iv[j]; vv.w *= iv[j];
            *(float4*)(Ah + (size_t)row*Sn + kc + cc*4) = vv;
            __nv_bfloat16 h0,l0,h1,l1,h2,l2,h3,l3;
            bsplit(vv.x,h0,l0); bsplit(vv.y,h1,l1); bsplit(vv.z,h2,l2); bsplit(vv.w,h3,l3);
            int wo = row*SA + cc*2;
            As0[wo]   = packbf(h0,h1); As0[wo+1] = packbf(h2,h3);
            As1[wo]   = packbf(l0,l1); As1[wo+1] = packbf(l2,l3);
        }
#pragma unroll
        for (int j = 0; j < 2; j++) {
            int g = tid + j*256;
            int row = g >> 3, cc = g & 7;
            int wo = row*SA + cc*2;
            *(uint2*)&Bs0[wo] = bv0[j];
            *(uint2*)&Bs1[wo] = bv1[j];
        }
        __syncthreads();
        // mma: 2 k16-steps x 8 ntiles x 3 products
#pragma unroll
        for (int s = 0; s < 2; s++) {
            uint32_t af0[4], af1[4];
            int base = (wid*16 + gid)*SA + s*8 + tig;
            af0[0] = As0[base];        af0[1] = As0[base + 8*SA];
            af0[2] = As0[base + 4];    af0[3] = As0[base + 8*SA + 4];
            af1[0] = As1[base];        af1[1] = As1[base + 8*SA];
            af1[2] = As1[base + 4];    af1[3] = As1[base + 8*SA + 4];
#pragma unroll
            for (int nt = 0; nt < 8; nt++) {
                int nb = (nt*8 + gid)*SA + s*8 + tig;
                uint32_t b00 = Bs0[nb], b01 = Bs0[nb + 4];
                uint32_t b10 = Bs1[nb], b11 = Bs1[nb + 4];
                mma_bf16(acc[nt], af0, b00, b01);   // a0*v0
                mma_bf16(acc[nt], af0, b10, b11);   // a0*v1
                mma_bf16(acc[nt], af1, b00, b01);   // a1*v0
            }
        }
    }

    // epilogue: ctx fp32 [b][s][h*64+dk]
    int sa = q0 + wid*16 + gid;
    int sb = sa + 8;
#pragma unroll
    for (int nt = 0; nt < 8; nt++) {
        int dk = nt*8 + tig*2;
        *(float2*)&ctx[((size_t)(b*Sn + sa))*Dn + h*DKn + dk] = make_float2(acc[nt].x, acc[nt].y);
        *(float2*)&ctx[((size_t)(b*Sn + sb))*Dn + h*DKn + dk] = make_float2(acc[nt].z, acc[nt].w);
    }
}

// ---------------------------------------------------------------------------
extern "C" void kernel_launch(void* const* d_in, const int* in_sizes, int n_in,
                              void* d_out, int out_size)
{
    const float* Q   = (const float*)d_in[0];
    const float* Wq  = (const float*)d_in[1];
    const float* bq  = (const float*)d_in[2];
    const float* Wk  = (const float*)d_in[3];
    const float* bk  = (const float*)d_in[4];
    const float* Wv  = (const float*)d_in[5];
    const float* bv  = (const float*)d_in[6];
    const int*   len = (const int*)d_in[7];

    float* ctx = (float*)d_out;
    float* attn;
    if ((size_t)out_size >= (size_t)CTX_ELEMS + ATT_ELEMS) {
        attn = ctx + CTX_ELEMS;   // tuple output: [context | attn]
    } else {
        void* p = nullptr;
        cudaGetSymbolAddress(&p, g_attn_fallback);
        attn = (float*)p;
    }

    // 0) bf16 hi/lo splits of inputs
    prep_x_kernel<<<dim3(CTX_ELEMS/4/256), 256>>>(Q);
    prep_w_kernel<<<dim3(3*Dn*Dn/4/256), 256>>>(Wq, Wk, Wv);
    // 1) QKV projections (tensor cores); q/k -> bf16 splits, v -> fp32
    qkv_mma_kernel<<<dim3(Dn/128, Mtot/128, 3), 256>>>(bq, bk, bv);
    // 1b) V^T bf16 splits
    vtrans_kernel<<<dim3(Sn/64, BH), 256>>>();
    // 2) scores (tensor cores): exp+mask+partials
    scores_mma_kernel<<<dim3(Sn/128, Sn/128, BH), 256>>>(len, attn);
    // 3) finish rowsums
    rowsum_reduce_kernel<<<dim3((BH*Sn + 255)/256), 256>>>();
    // 4) context = normalized attn @ V (tensor cores; normalizes attn in place)
    av_mma_kernel<<<dim3(Sn/128, BH), 256>>>(attn, ctx);
}

// round 6
// speedup vs baseline: 2.2901x; 1.1359x over previous
#include <cuda_runtime.h>
#include <cuda_bf16.h>
#include <math.h>
#include <stdint.h>

#define Bn   32
#define Sn   512
#define Dn   1024
#define Hn   16
#define DKn  64
#define BH   (Bn*Hn)                 // 512
#define Mtot (Bn*Sn)                 // 16384
#define CTX_ELEMS (Bn*Sn*Dn)         // 16,777,216
#define ATT_ELEMS ((size_t)Bn*Hn*Sn*Sn) // 134,217,728

// Scratch (allocation-free per harness rules)
__device__ float g_v[CTX_ELEMS];
__device__ float g_part[(size_t)BH*Sn*8];
__device__ float g_attn_fallback[ATT_ELEMS];
// bf16 hi/lo splits
__device__ __nv_bfloat16 g_xb0[CTX_ELEMS];
__device__ __nv_bfloat16 g_xb1[CTX_ELEMS];
__device__ __nv_bfloat16 g_wb0[3*Dn*Dn];
__device__ __nv_bfloat16 g_wb1[3*Dn*Dn];
__device__ __nv_bfloat16 g_qb0[CTX_ELEMS];
__device__ __nv_bfloat16 g_qb1[CTX_ELEMS];
__device__ __nv_bfloat16 g_kb0[CTX_ELEMS];
__device__ __nv_bfloat16 g_kb1[CTX_ELEMS];
__device__ __nv_bfloat16 g_vt0[CTX_ELEMS];   // V^T: [bh][dk=64][s=512]
__device__ __nv_bfloat16 g_vt1[CTX_ELEMS];

// ---------------- mma.sync bf16 (non-'a' tensor path, works on sm_103) -----
__device__ __forceinline__ void mma_bf16(float4& d, const uint32_t* a,
                                         uint32_t b0, uint32_t b1) {
    asm volatile(
        "mma.sync.aligned.m16n8k16.row.col.f32.bf16.bf16.f32 "
        "{%0,%1,%2,%3},{%4,%5,%6,%7},{%8,%9},{%0,%1,%2,%3};"
        : "+f"(d.x), "+f"(d.y), "+f"(d.z), "+f"(d.w)
        : "r"(a[0]), "r"(a[1]), "r"(a[2]), "r"(a[3]), "r"(b0), "r"(b1));
}

__device__ __forceinline__ void bsplit(float v, __nv_bfloat16& h, __nv_bfloat16& l) {
    h = __float2bfloat16(v);
    l = __float2bfloat16(v - __bfloat162float(h));
}
__device__ __forceinline__ uint32_t packbf(__nv_bfloat16 a, __nv_bfloat16 b) {
    __nv_bfloat162 t(a, b);
    return *(uint32_t*)&t;
}

// ---------------------------------------------------------------------------
// prep: bf16 hi/lo splits of X and the 3 weight matrices
// ---------------------------------------------------------------------------
__global__ __launch_bounds__(256) void prep_x_kernel(const float* __restrict__ X)
{
    size_t i = (size_t)blockIdx.x * 256 + threadIdx.x;
    float4 v = ((const float4*)X)[i];
    float f[4] = {v.x, v.y, v.z, v.w};
    __nv_bfloat16 b0[4], b1[4];
#pragma unroll
    for (int k = 0; k < 4; k++) bsplit(f[k], b0[k], b1[k]);
    ((uint32_t*)g_xb0)[i*2]   = packbf(b0[0], b0[1]);
    ((uint32_t*)g_xb0)[i*2+1] = packbf(b0[2], b0[3]);
    ((uint32_t*)g_xb1)[i*2]   = packbf(b1[0], b1[1]);
    ((uint32_t*)g_xb1)[i*2+1] = packbf(b1[2], b1[3]);
}

__global__ __launch_bounds__(256) void prep_w_kernel(
    const float* __restrict__ Wq, const float* __restrict__ Wk, const float* __restrict__ Wv)
{
    size_t i = (size_t)blockIdx.x * 256 + threadIdx.x;
    int z = (int)(i >> 18);
    const float* src = (z == 0) ? Wq : (z == 1) ? Wk : Wv;
    float4 v = ((const float4*)src)[i & 262143];
    float f[4] = {v.x, v.y, v.z, v.w};
    __nv_bfloat16 b0[4], b1[4];
#pragma unroll
    for (int k = 0; k < 4; k++) bsplit(f[k], b0[k], b1[k]);
    ((uint32_t*)g_wb0)[i*2]   = packbf(b0[0], b0[1]);
    ((uint32_t*)g_wb0)[i*2+1] = packbf(b0[2], b0[3]);
    ((uint32_t*)g_wb1)[i*2]   = packbf(b1[0], b1[1]);
    ((uint32_t*)g_wb1)[i*2+1] = packbf(b1[2], b1[3]);
}

// ---------------------------------------------------------------------------
// QKV projection via mma.sync bf16x3: C = X @ W^T + bias
// CTA 128x128, warp tile 32x64, 96 K-chunks (3 products x 32).
// q/k outputs written as bf16 hi/lo pairs; v as fp32.
// ---------------------------------------------------------------------------
#define SA 20   // smem row stride in words

__global__ __launch_bounds__(256, 2) void qkv_mma_kernel(
    const float* __restrict__ bq, const float* __restrict__ bk, const float* __restrict__ bv)
{
    __shared__ uint32_t As[2][128*SA];
    __shared__ uint32_t Bs[2][128*SA];

    const int tid  = threadIdx.x;
    const int wid  = tid >> 5;
    const int lane = tid & 31;
    const int gid  = lane >> 2;
    const int tig  = lane & 3;
    const int wm   = wid >> 1;
    const int wn   = wid & 1;
    const int z    = blockIdx.z;
    const int bm   = blockIdx.y * 128;
    const int bn   = blockIdx.x * 128;
    const size_t zoff = (size_t)z * Dn * Dn;

    const __nv_bfloat16* w0p = g_wb0 + zoff;
    const __nv_bfloat16* w1p = g_wb1 + zoff;

    const int r0 = tid >> 3;
    const int c4 = tid & 7;

    float4 acc[2][8];
#pragma unroll
    for (int mt = 0; mt < 2; mt++)
#pragma unroll
        for (int nt = 0; nt < 8; nt++) acc[mt][nt] = make_float4(0.f, 0.f, 0.f, 0.f);

    uint2 areg[4], breg[4];
    {
        const __nv_bfloat16* a = g_xb0 + (size_t)bm * Dn;
        const __nv_bfloat16* w = w0p   + (size_t)bn * Dn;
#pragma unroll
        for (int j = 0; j < 4; j++) {
            int row = r0 + j*32;
            areg[j] = *(const uint2*)(a + (size_t)row*Dn + c4*4);
            breg[j] = *(const uint2*)(w + (size_t)row*Dn + c4*4);
        }
#pragma unroll
        for (int j = 0; j < 4; j++) {
            int row = r0 + j*32;
            int wo = row*SA + c4*2;
            *(uint2*)&As[0][wo] = areg[j];
            *(uint2*)&Bs[0][wo] = breg[j];
        }
    }
    __syncthreads();

    for (int it = 0; it < 96; it++) {
        const int cur = it & 1;
        if (it + 1 < 96) {
            int p  = (it + 1) >> 5;
            int kc = ((it + 1) & 31) * 32;
            const __nv_bfloat16* a = ((p == 2) ? g_xb1 : g_xb0) + (size_t)bm * Dn + kc;
            const __nv_bfloat16* w = ((p == 1) ? w1p  : w0p  ) + (size_t)bn * Dn + kc;
#pragma unroll
            for (int j = 0; j < 4; j++) {
                int row = r0 + j*32;
                areg[j] = *(const uint2*)(a + (size_t)row*Dn + c4*4);
                breg[j] = *(const uint2*)(w + (size_t)row*Dn + c4*4);
            }
        }
#pragma unroll
        for (int s = 0; s < 2; s++) {
            uint32_t af[2][4];
#pragma unroll
            for (int mt = 0; mt < 2; mt++) {
                int base = (wm*32 + mt*16 + gid)*SA + s*8 + tig;
                af[mt][0] = As[cur][base];
                af[mt][1] = As[cur][base + 8*SA];
                af[mt][2] = As[cur][base + 4];
                af[mt][3] = As[cur][base + 8*SA + 4];
            }
#pragma unroll
            for (int nt = 0; nt < 8; nt++) {
                int nb = (wn*64 + nt*8 + gid)*SA + s*8 + tig;
                uint32_t b0 = Bs[cur][nb];
                uint32_t b1 = Bs[cur][nb + 4];
                mma_bf16(acc[0][nt], af[0], b0, b1);
                mma_bf16(acc[1][nt], af[1], b0, b1);
            }
        }
        if (it + 1 < 96) {
            const int nxt = (it + 1) & 1;
#pragma unroll
            for (int j = 0; j < 4; j++) {
                int row = r0 + j*32;
                int wo = row*SA + c4*2;
                *(uint2*)&As[nxt][wo] = areg[j];
                *(uint2*)&Bs[nxt][wo] = breg[j];
            }
            __syncthreads();
        }
    }

    const float* bias = (z == 0) ? bq : (z == 1) ? bk : bv;
    if (z == 2) {
        // V: fp32 [bh][s][dk]
#pragma unroll
        for (int mt = 0; mt < 2; mt++) {
            int rowa = bm + wm*32 + mt*16 + gid;
            int rowb = rowa + 8;
            int ba = rowa >> 9, sa = rowa & 511;
            int bb2 = rowb >> 9, sb = rowb & 511;
#pragma unroll
            for (int nt = 0; nt < 8; nt++) {
                int feat = bn + wn*64 + nt*8 + tig*2;
                int h = feat >> 6, dk = feat & 63;
                float2 bv2 = *(const float2*)&bias[feat];
                float2 v0 = make_float2(acc[mt][nt].x + bv2.x, acc[mt][nt].y + bv2.y);
                float2 v1 = make_float2(acc[mt][nt].z + bv2.x, acc[mt][nt].w + bv2.y);
                *(float2*)&g_v[((size_t)((ba *Hn + h)*Sn + sa))*DKn + dk] = v0;
                *(float2*)&g_v[((size_t)((bb2*Hn + h)*Sn + sb))*DKn + dk] = v1;
            }
        }
    } else {
        // Q/K: bf16 hi/lo pairs [bh][s][dk]
        __nv_bfloat16* o0 = (z == 0) ? g_qb0 : g_kb0;
        __nv_bfloat16* o1 = (z == 0) ? g_qb1 : g_kb1;
#pragma unroll
        for (int mt = 0; mt < 2; mt++) {
            int rowa = bm + wm*32 + mt*16 + gid;
            int rowb = rowa + 8;
            int ba = rowa >> 9, sa = rowa & 511;
            int bb2 = rowb >> 9, sb = rowb & 511;
#pragma unroll
            for (int nt = 0; nt < 8; nt++) {
                int feat = bn + wn*64 + nt*8 + tig*2;
                int h = feat >> 6, dk = feat & 63;
                float2 bv2 = *(const float2*)&bias[feat];
                float vx = acc[mt][nt].x + bv2.x, vy = acc[mt][nt].y + bv2.y;
                float vz = acc[mt][nt].z + bv2.x, vw = acc[mt][nt].w + bv2.y;
                __nv_bfloat16 hx,lx,hy,ly,hz,lz,hw,lw;
                bsplit(vx,hx,lx); bsplit(vy,hy,ly); bsplit(vz,hz,lz); bsplit(vw,hw,lw);
                size_t ia = ((size_t)((ba *Hn + h)*Sn + sa))*DKn + dk;
                size_t ib = ((size_t)((bb2*Hn + h)*Sn + sb))*DKn + dk;
                *(uint32_t*)&o0[ia] = packbf(hx,hy);
                *(uint32_t*)&o1[ia] = packbf(lx,ly);
                *(uint32_t*)&o0[ib] = packbf(hz,hw);
                *(uint32_t*)&o1[ib] = packbf(lz,lw);
            }
        }
    }
}

// ---------------------------------------------------------------------------
// vtrans: g_v fp32 [bh][s][64] -> bf16 hi/lo V^T [bh][64][512]
// ---------------------------------------------------------------------------
__global__ __launch_bounds__(256) void vtrans_kernel()
{
    const int bh = blockIdx.y;
    const int s0 = blockIdx.x * 64;
    __shared__ float T[64][65];
    const int tid = threadIdx.x;
#pragma unroll
    for (int j = 0; j < 4; j++) {
        int f = tid + j*256;
        int row = f >> 4, cc = (f & 15) * 4;
        float4 v = *(const float4*)&g_v[((size_t)bh*Sn + s0 + row)*DKn + cc];
        T[row][cc] = v.x; T[row][cc+1] = v.y; T[row][cc+2] = v.z; T[row][cc+3] = v.w;
    }
    __syncthreads();
#pragma unroll
    for (int j = 0; j < 8; j++) {
        int g = tid + j*256;
        int dk = g >> 5, sc = (g & 31) * 2;
        float va = T[sc][dk], vb = T[sc+1][dk];
        __nv_bfloat16 ha,la,hb,lb;
        bsplit(va,ha,la); bsplit(vb,hb,lb);
        size_t idx = ((size_t)bh*DKn + dk)*Sn + s0 + sc;
        *(uint32_t*)&g_vt0[idx] = packbf(ha,hb);
        *(uint32_t*)&g_vt1[idx] = packbf(la,lb);
    }
}

// ---------------------------------------------------------------------------
// scores via mma: E[q][k] = exp((q·k)/8)*mask, 128x128 tile per block.
// Fully-masked tiles (k0 >= length[b]) short-circuit to a zero-fill.
// ---------------------------------------------------------------------------
__global__ __launch_bounds__(256, 2) void scores_mma_kernel(
    const int* __restrict__ length, float* __restrict__ attn)
{
    __shared__ uint32_t As[2][128*SA];
    __shared__ uint32_t Bs[2][128*SA];

    const int tid  = threadIdx.x;
    const int wid  = tid >> 5;
    const int lane = tid & 31;
    const int gid  = lane >> 2;
    const int tig  = lane & 3;
    const int wm   = wid >> 1;
    const int wn   = wid & 1;
    const int bh = blockIdx.z;
    const int b  = bh >> 4;
    const int q0 = blockIdx.y * 128;
    const int k0 = blockIdx.x * 128;

    const int len = length[b];

    // ---- fully masked tile: write zeros, skip all compute -----------------
    if (k0 >= len) {
        float4 z4 = make_float4(0.f, 0.f, 0.f, 0.f);
#pragma unroll
        for (int j = 0; j < 16; j++) {
            int f = tid + j*256;              // 4096 float4 sites
            int row = f >> 5, cc = (f & 31) * 4;
            *(float4*)&attn[((size_t)bh*Sn + q0 + row)*Sn + k0 + cc] = z4;
        }
        if (tid < 128) {
            size_t pb = ((size_t)bh*Sn + q0 + tid)*8 + blockIdx.x*2;
            g_part[pb]     = 0.f;
            g_part[pb + 1] = 0.f;
        }
        return;
    }

    const int r0 = tid >> 3;
    const int c4 = tid & 7;

    const __nv_bfloat16* qs[2] = { g_qb0 + ((size_t)bh*Sn + q0)*DKn,
                                   g_qb1 + ((size_t)bh*Sn + q0)*DKn };
    const __nv_bfloat16* ks[2] = { g_kb0 + ((size_t)bh*Sn + k0)*DKn,
                                   g_kb1 + ((size_t)bh*Sn + k0)*DKn };
    const int pa[3] = {0, 0, 1};
    const int pb3[3] = {0, 1, 0};

    float4 acc[2][8];
#pragma unroll
    for (int mt = 0; mt < 2; mt++)
#pragma unroll
        for (int nt = 0; nt < 8; nt++) acc[mt][nt] = make_float4(0.f, 0.f, 0.f, 0.f);

    uint2 areg[4], breg[4];
    {
#pragma unroll
        for (int j = 0; j < 4; j++) {
            int row = r0 + j*32;
            areg[j] = *(const uint2*)(qs[0] + (size_t)row*DKn + c4*4);
            breg[j] = *(const uint2*)(ks[0] + (size_t)row*DKn + c4*4);
        }
#pragma unroll
        for (int j = 0; j < 4; j++) {
            int row = r0 + j*32;
            int wo = row*SA + c4*2;
            *(uint2*)&As[0][wo] = areg[j];
            *(uint2*)&Bs[0][wo] = breg[j];
        }
    }
    __syncthreads();

    for (int it = 0; it < 6; it++) {
        const int cur = it & 1;
        if (it + 1 < 6) {
            int p  = (it + 1) >> 1;
            int kc = ((it + 1) & 1) * 32;
            const __nv_bfloat16* a = qs[pa[p]] + kc;
            const __nv_bfloat16* w = ks[pb3[p]] + kc;
#pragma unroll
            for (int j = 0; j < 4; j++) {
                int row = r0 + j*32;
                areg[j] = *(const uint2*)(a + (size_t)row*DKn + c4*4);
                breg[j] = *(const uint2*)(w + (size_t)row*DKn + c4*4);
            }
        }
#pragma unroll
        for (int s = 0; s < 2; s++) {
            uint32_t af[2][4];
#pragma unroll
            for (int mt = 0; mt < 2; mt++) {
                int base = (wm*32 + mt*16 + gid)*SA + s*8 + tig;
                af[mt][0] = As[cur][base];
                af[mt][1] = As[cur][base + 8*SA];
                af[mt][2] = As[cur][base + 4];
                af[mt][3] = As[cur][base + 8*SA + 4];
            }
#pragma unroll
            for (int nt = 0; nt < 8; nt++) {
                int nb = (wn*64 + nt*8 + gid)*SA + s*8 + tig;
                uint32_t b0 = Bs[cur][nb];
                uint32_t b1 = Bs[cur][nb + 4];
                mma_bf16(acc[0][nt], af[0], b0, b1);
                mma_bf16(acc[1][nt], af[1], b0, b1);
            }
        }
        if (it + 1 < 6) {
            const int nxt = (it + 1) & 1;
#pragma unroll
            for (int j = 0; j < 4; j++) {
                int row = r0 + j*32;
                int wo = row*SA + c4*2;
                *(uint2*)&As[nxt][wo] = areg[j];
                *(uint2*)&Bs[nxt][wo] = breg[j];
            }
            __syncthreads();
        }
    }

    // epilogue: exp + mask + write + row partials
#pragma unroll
    for (int mt = 0; mt < 2; mt++) {
        int sa = q0 + wm*32 + mt*16 + gid;
        int sb = sa + 8;
        float rpa = 0.f, rpb = 0.f;
#pragma unroll
        for (int nt = 0; nt < 8; nt++) {
            int kc0 = k0 + wn*64 + nt*8 + tig*2;
            float4 a = acc[mt][nt];
            float ex = (kc0   < len) ? expf(a.x * 0.125f) : 0.f;
            float ey = (kc0+1 < len) ? expf(a.y * 0.125f) : 0.f;
            float ez = (kc0   < len) ? expf(a.z * 0.125f) : 0.f;
            float ew = (kc0+1 < len) ? expf(a.w * 0.125f) : 0.f;
            *(float2*)&attn[((size_t)bh*Sn + sa)*Sn + kc0] = make_float2(ex, ey);
            *(float2*)&attn[((size_t)bh*Sn + sb)*Sn + kc0] = make_float2(ez, ew);
            rpa += ex + ey;
            rpb += ez + ew;
        }
        rpa += __shfl_xor_sync(0xffffffffu, rpa, 1);
        rpa += __shfl_xor_sync(0xffffffffu, rpa, 2);
        rpb += __shfl_xor_sync(0xffffffffu, rpb, 1);
        rpb += __shfl_xor_sync(0xffffffffu, rpb, 2);
        if (tig == 0) {
            g_part[((size_t)bh*Sn + sa)*8 + blockIdx.x*2 + wn] = rpa;
            g_part[((size_t)bh*Sn + sb)*8 + blockIdx.x*2 + wn] = rpb;
        }
    }
}

// ---------------------------------------------------------------------------
// av via mma: ctx = (E @ V) * inv. M=128 q, N=64 dk, K bounded by length[b].
// Normalizes attn in place (masked columns are already zero and stay zero).
// Row sums folded in from g_part (8 partials per row).
// ---------------------------------------------------------------------------
__global__ __launch_bounds__(256, 2) void av_mma_kernel(
    const int* __restrict__ length, float* __restrict__ attn, float* __restrict__ ctx)
{
    __shared__ uint32_t As0[128*SA];
    __shared__ uint32_t As1[128*SA];
    __shared__ uint32_t Bs0[64*SA];
    __shared__ uint32_t Bs1[64*SA];
    __shared__ float invS[128];

    const int tid  = threadIdx.x;
    const int wid  = tid >> 5;
    const int lane = tid & 31;
    const int gid  = lane >> 2;
    const int tig  = lane & 3;
    const int bh = blockIdx.y;
    const int b  = bh >> 4;
    const int h  = bh & 15;
    const int q0 = blockIdx.x * 128;

    float* Ah = attn + ((size_t)bh*Sn + q0) * Sn;
    const __nv_bfloat16* vt0 = g_vt0 + (size_t)bh * DKn * Sn;
    const __nv_bfloat16* vt1 = g_vt1 + (size_t)bh * DKn * Sn;

    const int len = length[b];
    int kmax = (len + 31) & ~31;
    if (kmax > Sn) kmax = Sn;

    if (tid < 128) {
        const float* pp = &g_part[((size_t)bh*Sn + q0 + tid)*8];
        float4 p0 = *(const float4*)pp;
        float4 p1 = *(const float4*)(pp + 4);
        float s = p0.x + p0.y + p0.z + p0.w + p1.x + p1.y + p1.z + p1.w;
        invS[tid] = 1.0f / (s + 1e-8f);
    }

    float4 acc[8];
#pragma unroll
    for (int nt = 0; nt < 8; nt++) acc[nt] = make_float4(0.f, 0.f, 0.f, 0.f);

    for (int kc = 0; kc < kmax; kc += 32) {
        float4 av[4];
        float iv[4];
#pragma unroll
        for (int j = 0; j < 4; j++) {
            int f = tid + j*256;
            int row = f >> 3, cc = f & 7;
            av[j] = *(const float4*)(Ah + (size_t)row*Sn + kc + cc*4);
        }
        uint2 bv0[2], bv1[2];
#pragma unroll
        for (int j = 0; j < 2; j++) {
            int g = tid + j*256;
            int row = g >> 3, cc = g & 7;
            bv0[j] = *(const uint2*)(vt0 + (size_t)row*Sn + kc + cc*4);
            bv1[j] = *(const uint2*)(vt1 + (size_t)row*Sn + kc + cc*4);
        }
        __syncthreads();   // previous chunk's mma done; invS ready (first iter)
#pragma unroll
        for (int j = 0; j < 4; j++) {
            int f = tid + j*256;
            int row = f >> 3, cc = f & 7;
            iv[j] = invS[row];
            float4 vv = av[j];
            vv.x *= iv[j]; vv.y *= iv[j]; vv.z *= iv[j]; vv.w *= iv[j];
            *(float4*)(Ah + (size_t)row*Sn + kc + cc*4) = vv;
            __nv_bfloat16 h0,l0,h1,l1,h2,l2,h3,l3;
            bsplit(vv.x,h0,l0); bsplit(vv.y,h1,l1); bsplit(vv.z,h2,l2); bsplit(vv.w,h3,l3);
            int wo = row*SA + cc*2;
            As0[wo]   = packbf(h0,h1); As0[wo+1] = packbf(h2,h3);
            As1[wo]   = packbf(l0,l1); As1[wo+1] = packbf(l2,l3);
        }
#pragma unroll
        for (int j = 0; j < 2; j++) {
            int g = tid + j*256;
            int row = g >> 3, cc = g & 7;
            int wo = row*SA + cc*2;
            *(uint2*)&Bs0[wo] = bv0[j];
            *(uint2*)&Bs1[wo] = bv1[j];
        }
        __syncthreads();
#pragma unroll
        for (int s = 0; s < 2; s++) {
            uint32_t af0[4], af1[4];
            int base = (wid*16 + gid)*SA + s*8 + tig;
            af0[0] = As0[base];        af0[1] = As0[base + 8*SA];
            af0[2] = As0[base + 4];    af0[3] = As0[base + 8*SA + 4];
            af1[0] = As1[base];        af1[1] = As1[base + 8*SA];
            af1[2] = As1[base + 4];    af1[3] = As1[base + 8*SA + 4];
#pragma unroll
            for (int nt = 0; nt < 8; nt++) {
                int nb = (nt*8 + gid)*SA + s*8 + tig;
                uint32_t b00 = Bs0[nb], b01 = Bs0[nb + 4];
                uint32_t b10 = Bs1[nb], b11 = Bs1[nb + 4];
                mma_bf16(acc[nt], af0, b00, b01);   // a0*v0
                mma_bf16(acc[nt], af0, b10, b11);   // a0*v1
                mma_bf16(acc[nt], af1, b00, b01);   // a1*v0
            }
        }
    }

    // epilogue: ctx fp32 [b][s][h*64+dk]
    int sa = q0 + wid*16 + gid;
    int sb = sa + 8;
#pragma unroll
    for (int nt = 0; nt < 8; nt++) {
        int dk = nt*8 + tig*2;
        *(float2*)&ctx[((size_t)(b*Sn + sa))*Dn + h*DKn + dk] = make_float2(acc[nt].x, acc[nt].y);
        *(float2*)&ctx[((size_t)(b*Sn + sb))*Dn + h*DKn + dk] = make_float2(acc[nt].z, acc[nt].w);
    }
}

// ---------------------------------------------------------------------------
extern "C" void kernel_launch(void* const* d_in, const int* in_sizes, int n_in,
                              void* d_out, int out_size)
{
    const float* Q   = (const float*)d_in[0];
    const float* Wq  = (const float*)d_in[1];
    const float* bq  = (const float*)d_in[2];
    const float* Wk  = (const float*)d_in[3];
    const float* bk  = (const float*)d_in[4];
    const float* Wv  = (const float*)d_in[5];
    const float* bv  = (const float*)d_in[6];
    const int*   len = (const int*)d_in[7];

    float* ctx = (float*)d_out;
    float* attn;
    if ((size_t)out_size >= (size_t)CTX_ELEMS + ATT_ELEMS) {
        attn = ctx + CTX_ELEMS;   // tuple output: [context | attn]
    } else {
        void* p = nullptr;
        cudaGetSymbolAddress(&p, g_attn_fallback);
        attn = (float*)p;
    }

    // 0) bf16 hi/lo splits of inputs
    prep_x_kernel<<<dim3(CTX_ELEMS/4/256), 256>>>(Q);
    prep_w_kernel<<<dim3(3*Dn*Dn/4/256), 256>>>(Wq, Wk, Wv);
    // 1) QKV projections (tensor cores); q/k -> bf16 splits, v -> fp32
    qkv_mma_kernel<<<dim3(Dn/128, Mtot/128, 3), 256>>>(bq, bk, bv);
    // 1b) V^T bf16 splits
    vtrans_kernel<<<dim3(Sn/64, BH), 256>>>();
    // 2) scores (tensor cores): exp+mask+partials, masked tiles short-circuit
    scores_mma_kernel<<<dim3(Sn/128, Sn/128, BH), 256>>>(len, attn);
    // 3) context = (E @ V) * inv (tensor cores; normalizes attn in place,
    //    K-loop bounded by length[b], rowsums folded in from partials)
    av_mma_kernel<<<dim3(Sn/128, BH), 256>>>(len, attn, ctx);
}